// round 6
// baseline (speedup 1.0000x reference)
#include <cuda_runtime.h>
#include <cuda_bf16.h>
#include <cstdint>

#define BATCH 2
#define SEQ   2048
#define DIM   1024
#define NH    16
#define HDIM  64
#define MTOT  (BATCH * SEQ)   // 4096

// ---------------------------------------------------------------------------
// Scratch (allocation-free __device__ globals)
// ---------------------------------------------------------------------------
__device__ __align__(16) __nv_bfloat16 g_Xhi[(size_t)MTOT * DIM];
__device__ __align__(16) __nv_bfloat16 g_Xlo[(size_t)MTOT * DIM];
__device__ __align__(16) __nv_bfloat16 g_Ohi[(size_t)MTOT * DIM];
__device__ __align__(16) __nv_bfloat16 g_Olo[(size_t)MTOT * DIM];
__device__ __align__(16) __nv_bfloat16 g_Wall_hi[(size_t)3 * DIM * DIM];
__device__ __align__(16) __nv_bfloat16 g_Wall_lo[(size_t)3 * DIM * DIM];
__device__ __align__(16) __nv_bfloat16 g_Wohi[(size_t)DIM * DIM];
__device__ __align__(16) __nv_bfloat16 g_Wolo[(size_t)DIM * DIM];
__device__ float g_bias[3 * DIM];

// attention operands, per-head layouts
__device__ __align__(16) __nv_bfloat16 g_Qh[(size_t)BATCH * NH * SEQ * HDIM];
__device__ __align__(16) __nv_bfloat16 g_Ql[(size_t)BATCH * NH * SEQ * HDIM];
__device__ __align__(16) __nv_bfloat16 g_Kh[(size_t)BATCH * NH * SEQ * HDIM];
__device__ __align__(16) __nv_bfloat16 g_Kl[(size_t)BATCH * NH * SEQ * HDIM];
__device__ __align__(16) __nv_bfloat16 g_Vth[(size_t)BATCH * NH * HDIM * SEQ];
__device__ __align__(16) __nv_bfloat16 g_Vtl[(size_t)BATCH * NH * HDIM * SEQ];

// ---------------------------------------------------------------------------
// PTX helpers (arch-neutral)
// ---------------------------------------------------------------------------
__device__ __forceinline__ uint32_t smem_u32(const void* p) {
    uint32_t a;
    asm("{ .reg .u64 t; cvta.to.shared.u64 t, %1; cvt.u32.u64 %0, t; }"
        : "=r"(a) : "l"(p));
    return a;
}
__device__ __forceinline__ void cp16(uint32_t dst, const void* src) {
    asm volatile("cp.async.cg.shared.global [%0], [%1], 16;" :: "r"(dst), "l"(src));
}
__device__ __forceinline__ void cp_commit() {
    asm volatile("cp.async.commit_group;" ::: "memory");
}
__device__ __forceinline__ void cp_wait0() {
    asm volatile("cp.async.wait_group 0;" ::: "memory");
}
__device__ __forceinline__ void cp_wait1() {
    asm volatile("cp.async.wait_group 1;" ::: "memory");
}
__device__ __forceinline__ void cp_wait2() {
    asm volatile("cp.async.wait_group 2;" ::: "memory");
}
__device__ __forceinline__ void ldsm4(uint32_t* r, uint32_t addr) {
    asm volatile("ldmatrix.sync.aligned.m8n8.x4.shared.b16 {%0,%1,%2,%3}, [%4];"
        : "=r"(r[0]), "=r"(r[1]), "=r"(r[2]), "=r"(r[3]) : "r"(addr));
}
__device__ __forceinline__ void mma16816(float* d, const uint32_t* a, const uint32_t* b) {
    asm volatile("mma.sync.aligned.m16n8k16.row.col.f32.bf16.bf16.f32 "
        "{%0,%1,%2,%3}, {%4,%5,%6,%7}, {%8,%9}, {%0,%1,%2,%3};"
        : "+f"(d[0]), "+f"(d[1]), "+f"(d[2]), "+f"(d[3])
        : "r"(a[0]), "r"(a[1]), "r"(a[2]), "r"(a[3]), "r"(b[0]), "r"(b[1]));
}

// x,y -> bf16 hi pair (packed u32) + bf16 residual pair
__device__ __forceinline__ void split2(float x, float y, uint32_t& hi, uint32_t& lo) {
    __nv_bfloat162 h = __floats2bfloat162_rn(x, y);
    float hx = __bfloat162float(__low2bfloat16(h));
    float hy = __bfloat162float(__high2bfloat16(h));
    __nv_bfloat162 l = __floats2bfloat162_rn(x - hx, y - hy);
    hi = *(uint32_t*)&h;
    lo = *(uint32_t*)&l;
}

// ---------------------------------------------------------------------------
// small prep kernels
// ---------------------------------------------------------------------------
__global__ __launch_bounds__(256)
void split_kernel(const float4* __restrict__ x, __nv_bfloat162* __restrict__ hi,
                  __nv_bfloat162* __restrict__ lo, int n4)
{
    int i = blockIdx.x * 256 + threadIdx.x;
    if (i >= n4) return;
    float4 v = x[i];
    uint32_t h0, l0, h1, l1;
    split2(v.x, v.y, h0, l0);
    split2(v.z, v.w, h1, l1);
    *(uint32_t*)&hi[2 * i]     = h0;
    *(uint32_t*)&hi[2 * i + 1] = h1;
    *(uint32_t*)&lo[2 * i]     = l0;
    *(uint32_t*)&lo[2 * i + 1] = l1;
}

__global__ __launch_bounds__(256)
void pack_bias(const float* __restrict__ bq, const float* __restrict__ bk,
               const float* __restrict__ bv, float* __restrict__ out)
{
    int i = blockIdx.x * 256 + threadIdx.x;
    if (i >= 3 * DIM) return;
    out[i] = (i < DIM) ? bq[i] : (i < 2 * DIM) ? bk[i - DIM] : bv[i - 2 * DIM];
}

// ---------------------------------------------------------------------------
// bf16 split-GEMM via mma.sync, UNFOLDED: each 32-wide k-chunk loads
// Ahi/Alo/Whi/Wlo once; 3 products (hi*hi, hi*lo, lo*hi) reuse fragments.
// MODE 0: C[M,DIM] fp32 = A@W^T + bias
// MODE 1: QKV projection; epilogue scatters per-head bf16 hi/lo.
// ---------------------------------------------------------------------------
#define PADB 80
#define ATILE_B (128 * PADB)                 // 10240 per tensor tile
#define STAGE_B (4 * ATILE_B)                // Ahi,Alo,Whi,Wlo = 40960
#define NSTAGE 4
#define GEMM_SMEM (NSTAGE * STAGE_B)         // 163840
#define NCHUNK 32                            // K=1024 / 32

__device__ __forceinline__ void load_chunk(uint32_t st,
    const __nv_bfloat16* __restrict__ Ah, const __nv_bfloat16* __restrict__ Al,
    const __nv_bfloat16* __restrict__ Wh, const __nv_bfloat16* __restrict__ Wl,
    int k0, int tid)
{
    const int r = tid >> 2;                  // 0..63
    const int q = tid & 3;                   // 16B quarter of 64B row
    const uint32_t d0 = (uint32_t)r * PADB + q * 16;
    const uint32_t d1 = (uint32_t)(r + 64) * PADB + q * 16;
    const size_t g0 = (size_t)r * DIM + k0 + q * 8;
    const size_t g1 = (size_t)(r + 64) * DIM + k0 + q * 8;
    cp16(st + d0,                Ah + g0);
    cp16(st + d1,                Ah + g1);
    cp16(st + ATILE_B + d0,      Al + g0);
    cp16(st + ATILE_B + d1,      Al + g1);
    cp16(st + 2 * ATILE_B + d0,  Wh + g0);
    cp16(st + 2 * ATILE_B + d1,  Wh + g1);
    cp16(st + 3 * ATILE_B + d0,  Wl + g0);
    cp16(st + 3 * ATILE_B + d1,  Wl + g1);
    cp_commit();
}

template <int MODE>
__global__ __launch_bounds__(256)
void gemm_tc(const __nv_bfloat16* __restrict__ Ahi, const __nv_bfloat16* __restrict__ Alo,
             const __nv_bfloat16* __restrict__ Whi, const __nv_bfloat16* __restrict__ Wlo,
             const float* __restrict__ bias, float* __restrict__ C,
             __nv_bfloat16* __restrict__ Qh, __nv_bfloat16* __restrict__ Ql,
             __nv_bfloat16* __restrict__ Kh, __nv_bfloat16* __restrict__ Kl,
             __nv_bfloat16* __restrict__ Vth, __nv_bfloat16* __restrict__ Vtl)
{
    extern __shared__ char smr[];
    const uint32_t sb = smem_u32(smr);
    const int tid  = threadIdx.x;
    const int wid  = tid >> 5;
    const int lane = tid & 31;
    const int wr = wid >> 2;
    const int wc = wid & 3;
    const int m0 = blockIdx.y * 128;
    const int n0 = blockIdx.x * 128;

    const __nv_bfloat16* Ah = Ahi + (size_t)m0 * DIM;
    const __nv_bfloat16* Al = Alo + (size_t)m0 * DIM;
    const __nv_bfloat16* Wh = Whi + (size_t)n0 * DIM;
    const __nv_bfloat16* Wl = Wlo + (size_t)n0 * DIM;

    float c[4][4][4];
    #pragma unroll
    for (int i = 0; i < 4; i++)
        #pragma unroll
        for (int j = 0; j < 4; j++)
            #pragma unroll
            for (int e = 0; e < 4; e++) c[i][j][e] = 0.f;

    #pragma unroll
    for (int p = 0; p < 3; p++)
        load_chunk(sb + (uint32_t)p * STAGE_B, Ah, Al, Wh, Wl, p * 32, tid);

    const uint32_t a_row  = (uint32_t)(lane & 15);
    const uint32_t a_koff = (uint32_t)((lane >> 4) * 8);
    const uint32_t b_row  = (uint32_t)(((lane >> 4) << 3) + (lane & 7));
    const uint32_t b_koff = (uint32_t)(((lane >> 3) & 1) * 8);

    for (int ch = 0; ch < NCHUNK; ch++) {
        cp_wait2();
        __syncthreads();

        const int nc = ch + 3;
        if (nc < NCHUNK)
            load_chunk(sb + (uint32_t)(nc & 3) * STAGE_B, Ah, Al, Wh, Wl,
                       nc * 32, tid);
        else
            cp_commit();

        const uint32_t sAh = sb + (uint32_t)(ch & 3) * STAGE_B;
        const uint32_t sAl = sAh + ATILE_B;
        const uint32_t sWh = sAh + 2 * ATILE_B;
        const uint32_t sWl = sAh + 3 * ATILE_B;

        #pragma unroll
        for (int h = 0; h < 2; h++) {
            const uint32_t acol = (h * 16 + a_koff) * 2;
            const uint32_t bcol = (h * 16 + b_koff) * 2;
            const uint32_t aro  = (wr * 64 + a_row) * PADB + acol;
            const uint32_t bro  = (wc * 32 + b_row) * PADB + bcol;

            uint32_t ah[4][4], bh[2][4];
            #pragma unroll
            for (int i = 0; i < 4; i++)
                ldsm4(ah[i], sAh + aro + i * 16 * PADB);
            #pragma unroll
            for (int jp = 0; jp < 2; jp++)
                ldsm4(bh[jp], sWh + bro + jp * 16 * PADB);

            // hi * hi
            #pragma unroll
            for (int i = 0; i < 4; i++) {
                mma16816(c[i][0], ah[i], &bh[0][0]);
                mma16816(c[i][1], ah[i], &bh[0][2]);
                mma16816(c[i][2], ah[i], &bh[1][0]);
                mma16816(c[i][3], ah[i], &bh[1][2]);
            }

            // hi * lo
            {
                uint32_t bl[2][4];
                #pragma unroll
                for (int jp = 0; jp < 2; jp++)
                    ldsm4(bl[jp], sWl + bro + jp * 16 * PADB);
                #pragma unroll
                for (int i = 0; i < 4; i++) {
                    mma16816(c[i][0], ah[i], &bl[0][0]);
                    mma16816(c[i][1], ah[i], &bl[0][2]);
                    mma16816(c[i][2], ah[i], &bl[1][0]);
                    mma16816(c[i][3], ah[i], &bl[1][2]);
                }
            }

            // lo * hi
            {
                uint32_t al[4][4];
                #pragma unroll
                for (int i = 0; i < 4; i++)
                    ldsm4(al[i], sAl + aro + i * 16 * PADB);
                #pragma unroll
                for (int i = 0; i < 4; i++) {
                    mma16816(c[i][0], al[i], &bh[0][0]);
                    mma16816(c[i][1], al[i], &bh[0][2]);
                    mma16816(c[i][2], al[i], &bh[1][0]);
                    mma16816(c[i][3], al[i], &bh[1][2]);
                }
            }
        }
    }
    cp_wait0();

    const int g   = lane >> 2;
    const int tig = lane & 3;

    if (MODE == 0) {
        #pragma unroll
        for (int i = 0; i < 4; i++) {
            const int r0 = m0 + wr * 64 + i * 16 + g;
            #pragma unroll
            for (int j = 0; j < 4; j++) {
                const int cb = n0 + wc * 32 + j * 8 + 2 * tig;
                const float b0 = bias[cb], b1 = bias[cb + 1];
                float2 v0 = make_float2(c[i][j][0] + b0, c[i][j][1] + b1);
                float2 v1 = make_float2(c[i][j][2] + b0, c[i][j][3] + b1);
                *(float2*)(C + (size_t)r0 * DIM + cb)       = v0;
                *(float2*)(C + (size_t)(r0 + 8) * DIM + cb) = v1;
            }
        }
    } else {
        const int sec = n0 >> 10;            // 0=Q, 1=K, 2=V
        const int b   = m0 >> 11;            // batch
        const int sb0 = (m0 & 2047) + wr * 64 + g;
        #pragma unroll
        for (int i = 0; i < 4; i++) {
            const int s = sb0 + i * 16;      // rows s and s+8
            #pragma unroll
            for (int j = 0; j < 4; j++) {
                const int col = n0 + wc * 32 + j * 8 + 2 * tig;
                const int lc  = col & 1023;
                const int h   = lc >> 6;
                const int d   = lc & 63;
                const int bh  = b * NH + h;
                const float b0 = bias[col], b1 = bias[col + 1];
                const float v00 = c[i][j][0] + b0, v01 = c[i][j][1] + b1;
                const float v10 = c[i][j][2] + b0, v11 = c[i][j][3] + b1;
                if (sec < 2) {
                    __nv_bfloat16* Dh = (sec == 0) ? Qh : Kh;
                    __nv_bfloat16* Dl = (sec == 0) ? Ql : Kl;
                    uint32_t h0, l0, h1, l1;
                    split2(v00, v01, h0, l0);
                    split2(v10, v11, h1, l1);
                    const size_t o0 = ((size_t)bh * SEQ + s) * HDIM + d;
                    *(uint32_t*)(Dh + o0)              = h0;
                    *(uint32_t*)(Dl + o0)              = l0;
                    *(uint32_t*)(Dh + o0 + 8 * HDIM)   = h1;
                    *(uint32_t*)(Dl + o0 + 8 * HDIM)   = l1;
                } else {
                    const size_t vb0 = ((size_t)bh * HDIM + d) * SEQ + s;
                    const size_t vb1 = vb0 + SEQ;    // d+1
                    __nv_bfloat16 h00 = __float2bfloat16_rn(v00);
                    __nv_bfloat16 h01 = __float2bfloat16_rn(v01);
                    __nv_bfloat16 h10 = __float2bfloat16_rn(v10);
                    __nv_bfloat16 h11 = __float2bfloat16_rn(v11);
                    Vth[vb0]     = h00;
                    Vth[vb1]     = h01;
                    Vth[vb0 + 8] = h10;
                    Vth[vb1 + 8] = h11;
                    Vtl[vb0]     = __float2bfloat16_rn(v00 - __bfloat162float(h00));
                    Vtl[vb1]     = __float2bfloat16_rn(v01 - __bfloat162float(h01));
                    Vtl[vb0 + 8] = __float2bfloat16_rn(v10 - __bfloat162float(h10));
                    Vtl[vb1 + 8] = __float2bfloat16_rn(v11 - __bfloat162float(h11));
                }
            }
        }
    }
}

// ---------------------------------------------------------------------------
// Causal flash attention on HMMA, bf16 hi/lo split (3-product).
// ---------------------------------------------------------------------------
#define APAD 144
#define ATT_Q_BYTES (128 * APAD)
#define ATT_T_BYTES (64 * APAD)
#define ATT_STAGE   (4 * ATT_T_BYTES)
#define ATT_SMEM    (2 * ATT_Q_BYTES + 2 * ATT_STAGE)   // 110592

__device__ __forceinline__ void load_kv(uint32_t dst,
    const __nv_bfloat16* __restrict__ Khp, const __nv_bfloat16* __restrict__ Klp,
    const __nv_bfloat16* __restrict__ Vhp, const __nv_bfloat16* __restrict__ Vlp,
    int j, int tid)
{
    const int r  = tid >> 2;
    const int c0 = tid & 3;
    const uint32_t ro = (uint32_t)r * APAD;
    const size_t kg = (size_t)(j * 64 + r) * HDIM;
    const size_t vg = (size_t)r * SEQ + j * 64;
    cp16(dst + ro + c0 * 16,                    Khp + kg + c0 * 8);
    cp16(dst + ro + (c0 + 4) * 16,              Khp + kg + (c0 + 4) * 8);
    cp16(dst + ATT_T_BYTES + ro + c0 * 16,       Klp + kg + c0 * 8);
    cp16(dst + ATT_T_BYTES + ro + (c0 + 4) * 16, Klp + kg + (c0 + 4) * 8);
    cp16(dst + 2 * ATT_T_BYTES + ro + c0 * 16,       Vhp + vg + c0 * 8);
    cp16(dst + 2 * ATT_T_BYTES + ro + (c0 + 4) * 16, Vhp + vg + (c0 + 4) * 8);
    cp16(dst + 3 * ATT_T_BYTES + ro + c0 * 16,       Vlp + vg + c0 * 8);
    cp16(dst + 3 * ATT_T_BYTES + ro + (c0 + 4) * 16, Vlp + vg + (c0 + 4) * 8);
    cp_commit();
}

__global__ __launch_bounds__(256)
void attn_mma(const __nv_bfloat16* __restrict__ Qh, const __nv_bfloat16* __restrict__ Ql,
              const __nv_bfloat16* __restrict__ Kh, const __nv_bfloat16* __restrict__ Kl,
              const __nv_bfloat16* __restrict__ Vth, const __nv_bfloat16* __restrict__ Vtl,
              __nv_bfloat16* __restrict__ Ohi, __nv_bfloat16* __restrict__ Olo)
{
    extern __shared__ char smr[];
    const uint32_t sbse = smem_u32(smr);
    const uint32_t sQh = sbse;
    const uint32_t sQl = sbse + ATT_Q_BYTES;
    const uint32_t skv = sbse + 2 * ATT_Q_BYTES;

    const int tid  = threadIdx.x;
    const int w    = tid >> 5;
    const int lane = tid & 31;
    const int g    = lane >> 2;
    const int t    = lane & 3;
    const int qt   = 15 - blockIdx.x;
    const int bh   = blockIdx.y;
    const int b    = bh >> 4;
    const int h    = bh & 15;

    const __nv_bfloat16* Qhp = Qh + ((size_t)bh * SEQ + qt * 128) * HDIM;
    const __nv_bfloat16* Qlp = Ql + ((size_t)bh * SEQ + qt * 128) * HDIM;
    const __nv_bfloat16* Khp = Kh + (size_t)bh * SEQ * HDIM;
    const __nv_bfloat16* Klp = Kl + (size_t)bh * SEQ * HDIM;
    const __nv_bfloat16* Vhp = Vth + (size_t)bh * HDIM * SEQ;
    const __nv_bfloat16* Vlp = Vtl + (size_t)bh * HDIM * SEQ;

    #pragma unroll
    for (int i = 0; i < 4; i++) {
        int idx = tid + i * 256;
        int r = idx >> 3, q = idx & 7;
        cp16(sQh + (uint32_t)r * APAD + q * 16, Qhp + (size_t)r * HDIM + q * 8);
        cp16(sQl + (uint32_t)r * APAD + q * 16, Qlp + (size_t)r * HDIM + q * 8);
    }
    cp_commit();
    load_kv(skv, Khp, Klp, Vhp, Vlp, 0, tid);
    cp_wait1();
    __syncthreads();

    const uint32_t a_row  = (uint32_t)(lane & 15);
    const uint32_t a_koff = (uint32_t)((lane >> 4) * 8);
    const uint32_t b_row  = (uint32_t)(((lane >> 4) << 3) + (lane & 7));
    const uint32_t b_koff = (uint32_t)(((lane >> 3) & 1) * 8);

    uint32_t qhi[4][4], qlo[4][4];
    #pragma unroll
    for (int h4 = 0; h4 < 4; h4++) {
        uint32_t col = (h4 * 16 + a_koff) * 2;
        ldsm4(qhi[h4], sQh + (w * 16 + a_row) * APAD + col);
        ldsm4(qlo[h4], sQl + (w * 16 + a_row) * APAD + col);
    }

    float o[8][4];
    #pragma unroll
    for (int nb = 0; nb < 8; nb++)
        #pragma unroll
        for (int e = 0; e < 4; e++) o[nb][e] = 0.f;
    float mi0 = -1e30f, mi1 = -1e30f, li0 = 0.f, li1 = 0.f;

    const int sq0 = qt * 128 + w * 16 + g;
    const int njt = 2 * qt + 2;
    const float CE = 0.125f * 1.4426950408889634f;

    for (int j = 0; j < njt; j++) {
        if (j + 1 < njt) load_kv(skv + ((j + 1) & 1) * ATT_STAGE,
                                 Khp, Klp, Vhp, Vlp, j + 1, tid);
        else             cp_commit();
        cp_wait1();
        __syncthreads();

        const uint32_t sK = skv + (j & 1) * ATT_STAGE;

        float s[8][4];
        #pragma unroll
        for (int nb = 0; nb < 8; nb++)
            #pragma unroll
            for (int e = 0; e < 4; e++) s[nb][e] = 0.f;

        #pragma unroll
        for (int h4 = 0; h4 < 4; h4++) {
            const uint32_t col = (h4 * 16 + b_koff) * 2;
            #pragma unroll
            for (int jp = 0; jp < 4; jp++) {
                uint32_t kb[4], kl[4];
                ldsm4(kb, sK + (jp * 16 + b_row) * APAD + col);
                ldsm4(kl, sK + ATT_T_BYTES + (jp * 16 + b_row) * APAD + col);
                mma16816(s[2 * jp],     qhi[h4], kb);
                mma16816(s[2 * jp + 1], qhi[h4], kb + 2);
                mma16816(s[2 * jp],     qlo[h4], kb);
                mma16816(s[2 * jp + 1], qlo[h4], kb + 2);
                mma16816(s[2 * jp],     qhi[h4], kl);
                mma16816(s[2 * jp + 1], qhi[h4], kl + 2);
            }
        }

        const int kb0 = j * 64 + 2 * t;
        #pragma unroll
        for (int nb = 0; nb < 8; nb++) {
            const int c0 = kb0 + nb * 8;
            if (c0     > sq0)     s[nb][0] = -1e30f;
            if (c0 + 1 > sq0)     s[nb][1] = -1e30f;
            if (c0     > sq0 + 8) s[nb][2] = -1e30f;
            if (c0 + 1 > sq0 + 8) s[nb][3] = -1e30f;
        }

        float m0 = -1e30f, m1 = -1e30f;
        #pragma unroll
        for (int nb = 0; nb < 8; nb++) {
            m0 = fmaxf(m0, fmaxf(s[nb][0], s[nb][1]));
            m1 = fmaxf(m1, fmaxf(s[nb][2], s[nb][3]));
        }
        m0 = fmaxf(m0, __shfl_xor_sync(0xFFFFFFFFu, m0, 1));
        m0 = fmaxf(m0, __shfl_xor_sync(0xFFFFFFFFu, m0, 2));
        m1 = fmaxf(m1, __shfl_xor_sync(0xFFFFFFFFu, m1, 1));
        m1 = fmaxf(m1, __shfl_xor_sync(0xFFFFFFFFu, m1, 2));
        const float mn0 = fmaxf(mi0, m0), mn1 = fmaxf(mi1, m1);
        const float corr0 = exp2f((mi0 - mn0) * CE);
        const float corr1 = exp2f((mi1 - mn1) * CE);

        float rs0 = 0.f, rs1 = 0.f;
        #pragma unroll
        for (int nb = 0; nb < 8; nb++) {
            s[nb][0] = exp2f((s[nb][0] - mn0) * CE);
            s[nb][1] = exp2f((s[nb][1] - mn0) * CE);
            s[nb][2] = exp2f((s[nb][2] - mn1) * CE);
            s[nb][3] = exp2f((s[nb][3] - mn1) * CE);
            rs0 += s[nb][0] + s[nb][1];
            rs1 += s[nb][2] + s[nb][3];
        }
        rs0 += __shfl_xor_sync(0xFFFFFFFFu, rs0, 1);
        rs0 += __shfl_xor_sync(0xFFFFFFFFu, rs0, 2);
        rs1 += __shfl_xor_sync(0xFFFFFFFFu, rs1, 1);
        rs1 += __shfl_xor_sync(0xFFFFFFFFu, rs1, 2);
        li0 = li0 * corr0 + rs0;
        li1 = li1 * corr1 + rs1;
        mi0 = mn0; mi1 = mn1;

        #pragma unroll
        for (int nb = 0; nb < 8; nb++) {
            o[nb][0] *= corr0; o[nb][1] *= corr0;
            o[nb][2] *= corr1; o[nb][3] *= corr1;
        }

        uint32_t phi[4][4], plo[4][4];
        #pragma unroll
        for (int h4 = 0; h4 < 4; h4++) {
            split2(s[2 * h4][0],     s[2 * h4][1],     phi[h4][0], plo[h4][0]);
            split2(s[2 * h4][2],     s[2 * h4][3],     phi[h4][1], plo[h4][1]);
            split2(s[2 * h4 + 1][0], s[2 * h4 + 1][1], phi[h4][2], plo[h4][2]);
            split2(s[2 * h4 + 1][2], s[2 * h4 + 1][3], phi[h4][3], plo[h4][3]);
        }

        #pragma unroll
        for (int h4 = 0; h4 < 4; h4++) {
            const uint32_t col = (h4 * 16 + b_koff) * 2;
            #pragma unroll
            for (int jp = 0; jp < 4; jp++) {
                uint32_t vb[4], vl[4];
                ldsm4(vb, sK + 2 * ATT_T_BYTES + (jp * 16 + b_row) * APAD + col);
                ldsm4(vl, sK + 3 * ATT_T_BYTES + (jp * 16 + b_row) * APAD + col);
                mma16816(o[2 * jp],     phi[h4], vb);
                mma16816(o[2 * jp + 1], phi[h4], vb + 2);
                mma16816(o[2 * jp],     plo[h4], vb);
                mma16816(o[2 * jp + 1], plo[h4], vb + 2);
                mma16816(o[2 * jp],     phi[h4], vl);
                mma16816(o[2 * jp + 1], phi[h4], vl + 2);
            }
        }
        __syncthreads();
    }

    const float inv0 = 1.f / li0;
    const float inv1 = 1.f / li1;
    const size_t ob = (size_t)(b * SEQ + sq0) * DIM + h * HDIM;
    #pragma unroll
    for (int nb = 0; nb < 8; nb++) {
        const int d = nb * 8 + 2 * t;
        uint32_t h0, l0, h1, l1;
        split2(o[nb][0] * inv0, o[nb][1] * inv0, h0, l0);
        split2(o[nb][2] * inv1, o[nb][3] * inv1, h1, l1);
        *(uint32_t*)(Ohi + ob + d)           = h0;
        *(uint32_t*)(Olo + ob + d)           = l0;
        *(uint32_t*)(Ohi + ob + 8 * DIM + d) = h1;
        *(uint32_t*)(Olo + ob + 8 * DIM + d) = l1;
    }
}

// ---------------------------------------------------------------------------
// Launch.  Launch #6 = QKV gemm (ncu -s 5 -c 1 target).
// ---------------------------------------------------------------------------
extern "C" void kernel_launch(void* const* d_in, const int* in_sizes, int n_in,
                              void* d_out, int out_size)
{
    const float* X  = (const float*)d_in[0];
    const float* Wq = (const float*)d_in[1];
    const float* bq = (const float*)d_in[2];
    const float* Wk = (const float*)d_in[3];
    const float* bk = (const float*)d_in[4];
    const float* Wv = (const float*)d_in[5];
    const float* bv = (const float*)d_in[6];
    const float* Wo = (const float*)d_in[7];
    const float* bo = (const float*)d_in[8];
    float* out = (float*)d_out;

    float* bias;
    cudaGetSymbolAddress((void**)&bias, g_bias);

    __nv_bfloat16 *Xhi, *Xlo, *Ohi, *Olo, *Wah, *Wal, *Woh, *Wol;
    __nv_bfloat16 *Qh, *Ql, *Kh, *Kl, *Vth, *Vtl;
    cudaGetSymbolAddress((void**)&Xhi, g_Xhi);
    cudaGetSymbolAddress((void**)&Xlo, g_Xlo);
    cudaGetSymbolAddress((void**)&Ohi, g_Ohi);
    cudaGetSymbolAddress((void**)&Olo, g_Olo);
    cudaGetSymbolAddress((void**)&Wah, g_Wall_hi);
    cudaGetSymbolAddress((void**)&Wal, g_Wall_lo);
    cudaGetSymbolAddress((void**)&Woh, g_Wohi);
    cudaGetSymbolAddress((void**)&Wol, g_Wolo);
    cudaGetSymbolAddress((void**)&Qh, g_Qh);
    cudaGetSymbolAddress((void**)&Ql, g_Ql);
    cudaGetSymbolAddress((void**)&Kh, g_Kh);
    cudaGetSymbolAddress((void**)&Kl, g_Kl);
    cudaGetSymbolAddress((void**)&Vth, g_Vth);
    cudaGetSymbolAddress((void**)&Vtl, g_Vtl);

    cudaFuncSetAttribute(gemm_tc<0>, cudaFuncAttributeMaxDynamicSharedMemorySize, GEMM_SMEM);
    cudaFuncSetAttribute(gemm_tc<1>, cudaFuncAttributeMaxDynamicSharedMemorySize, GEMM_SMEM);
    cudaFuncSetAttribute(attn_mma, cudaFuncAttributeMaxDynamicSharedMemorySize, ATT_SMEM);

    const int nX4 = MTOT * DIM / 4;
    const int nW4 = DIM * DIM / 4;
    const size_t W1 = (size_t)DIM * DIM;

    // launches 1-5
    pack_bias<<<12, 256>>>(bq, bk, bv, bias);
    split_kernel<<<nX4 / 256, 256>>>((const float4*)X, (__nv_bfloat162*)Xhi,
                                     (__nv_bfloat162*)Xlo, nX4);
    split_kernel<<<nW4 / 256, 256>>>((const float4*)Wq, (__nv_bfloat162*)Wah,
                                     (__nv_bfloat162*)Wal, nW4);
    split_kernel<<<nW4 / 256, 256>>>((const float4*)Wk, (__nv_bfloat162*)(Wah + W1),
                                     (__nv_bfloat162*)(Wal + W1), nW4);
    split_kernel<<<nW4 / 256, 256>>>((const float4*)Wv, (__nv_bfloat162*)(Wah + 2 * W1),
                                     (__nv_bfloat162*)(Wal + 2 * W1), nW4);

    // launch 6: fused QKV projection with per-head split epilogue
    gemm_tc<1><<<dim3(3 * DIM / 128, MTOT / 128), 256, GEMM_SMEM>>>(
        Xhi, Xlo, Wah, Wal, bias, nullptr, Qh, Ql, Kh, Kl, Vth, Vtl);

    // launch 7: attention (writes Ohi/Olo)
    attn_mma<<<dim3(SEQ / 128, BATCH * NH), 256, ATT_SMEM>>>(
        Qh, Ql, Kh, Kl, Vth, Vtl, Ohi, Olo);

    // launches 8-9: Wo split + output projection
    split_kernel<<<nW4 / 256, 256>>>((const float4*)Wo, (__nv_bfloat162*)Woh,
                                     (__nv_bfloat162*)Wol, nW4);
    gemm_tc<0><<<dim3(DIM / 128, MTOT / 128), 256, GEMM_SMEM>>>(
        Ohi, Olo, Woh, Wol, bo, out,
        nullptr, nullptr, nullptr, nullptr, nullptr, nullptr);
}

// round 7
// speedup vs baseline: 2.4098x; 2.4098x over previous
#include <cuda_runtime.h>
#include <cuda_fp16.h>
#include <cstdint>

#define BATCH 2
#define SEQ   2048
#define DIM   1024
#define NH    16
#define HDIM  64
#define MTOT  (BATCH * SEQ)   // 4096

// ---------------------------------------------------------------------------
// Scratch (allocation-free __device__ globals), all fp16
// ---------------------------------------------------------------------------
__device__ __align__(16) __half g_Xh[(size_t)MTOT * DIM];
__device__ __align__(16) __half g_Oh[(size_t)MTOT * DIM];          // attn out
__device__ __align__(16) __half g_Wall[(size_t)3 * DIM * DIM];     // Wq|Wk|Wv
__device__ __align__(16) __half g_Wo_h[(size_t)DIM * DIM];
__device__ float g_bias[3 * DIM];

// attention operands, per-head layouts
__device__ __align__(16) __half g_Q[(size_t)BATCH * NH * SEQ * HDIM];
__device__ __align__(16) __half g_K[(size_t)BATCH * NH * SEQ * HDIM];
__device__ __align__(16) __half g_Vt[(size_t)BATCH * NH * HDIM * SEQ];

// ---------------------------------------------------------------------------
// PTX helpers (arch-neutral)
// ---------------------------------------------------------------------------
__device__ __forceinline__ uint32_t smem_u32(const void* p) {
    uint32_t a;
    asm("{ .reg .u64 t; cvta.to.shared.u64 t, %1; cvt.u32.u64 %0, t; }"
        : "=r"(a) : "l"(p));
    return a;
}
__device__ __forceinline__ void cp16(uint32_t dst, const void* src) {
    asm volatile("cp.async.cg.shared.global [%0], [%1], 16;" :: "r"(dst), "l"(src));
}
__device__ __forceinline__ void cp_commit() {
    asm volatile("cp.async.commit_group;" ::: "memory");
}
__device__ __forceinline__ void cp_wait0() {
    asm volatile("cp.async.wait_group 0;" ::: "memory");
}
__device__ __forceinline__ void cp_wait1() {
    asm volatile("cp.async.wait_group 1;" ::: "memory");
}
__device__ __forceinline__ void cp_wait2() {
    asm volatile("cp.async.wait_group 2;" ::: "memory");
}
__device__ __forceinline__ void cp_wait3() {
    asm volatile("cp.async.wait_group 3;" ::: "memory");
}
__device__ __forceinline__ void ldsm4(uint32_t* r, uint32_t addr) {
    asm volatile("ldmatrix.sync.aligned.m8n8.x4.shared.b16 {%0,%1,%2,%3}, [%4];"
        : "=r"(r[0]), "=r"(r[1]), "=r"(r[2]), "=r"(r[3]) : "r"(addr));
}
__device__ __forceinline__ void mma16816(float* d, const uint32_t* a, const uint32_t* b) {
    asm volatile("mma.sync.aligned.m16n8k16.row.col.f32.f16.f16.f32 "
        "{%0,%1,%2,%3}, {%4,%5,%6,%7}, {%8,%9}, {%0,%1,%2,%3};"
        : "+f"(d[0]), "+f"(d[1]), "+f"(d[2]), "+f"(d[3])
        : "r"(a[0]), "r"(a[1]), "r"(a[2]), "r"(a[3]), "r"(b[0]), "r"(b[1]));
}
__device__ __forceinline__ uint32_t packh2(float x, float y) {
    __half2 h = __floats2half2_rn(x, y);
    return *(uint32_t*)&h;
}

// ---------------------------------------------------------------------------
// prep kernels
// ---------------------------------------------------------------------------
__global__ __launch_bounds__(256)
void h_convert(const float4* __restrict__ x, uint32_t* __restrict__ out, int n4)
{
    int i = blockIdx.x * 256 + threadIdx.x;
    if (i >= n4) return;
    float4 v = x[i];
    out[2 * i]     = packh2(v.x, v.y);
    out[2 * i + 1] = packh2(v.z, v.w);
}

__global__ __launch_bounds__(256)
void pack_bias(const float* __restrict__ bq, const float* __restrict__ bk,
               const float* __restrict__ bv, float* __restrict__ out)
{
    int i = blockIdx.x * 256 + threadIdx.x;
    if (i >= 3 * DIM) return;
    out[i] = (i < DIM) ? bq[i] : (i < 2 * DIM) ? bk[i - DIM] : bv[i - 2 * DIM];
}

// ---------------------------------------------------------------------------
// fp16 GEMM via mma.sync:  C = A @ W^T (+ bias)
// MODE 0: fp32 C[M,DIM] output
// MODE 1: QKV projection; epilogue scatters per-head fp16 Q,K and transposed V
// CTA tile 128x128, BK=32 chunks, 5-stage cp.async pipeline, 2 CTAs/SM.
// ---------------------------------------------------------------------------
#define PADB 80
#define ATILE_B (128 * PADB)                 // 10240
#define STAGE_B (2 * ATILE_B)                // A + W = 20480
#define NSTAGE 5
#define GEMM_SMEM (NSTAGE * STAGE_B)         // 102400
#define NCHUNK 32

__device__ __forceinline__ void load_chunk(uint32_t st,
    const __half* __restrict__ A, const __half* __restrict__ W,
    int k0, int tid)
{
    const int r = tid >> 2;                  // 0..63
    const int q = tid & 3;                   // 16B quarter of 64B row
    const uint32_t d0 = (uint32_t)r * PADB + q * 16;
    const uint32_t d1 = (uint32_t)(r + 64) * PADB + q * 16;
    const size_t g0 = (size_t)r * DIM + k0 + q * 8;
    const size_t g1 = (size_t)(r + 64) * DIM + k0 + q * 8;
    cp16(st + d0,           A + g0);
    cp16(st + d1,           A + g1);
    cp16(st + ATILE_B + d0, W + g0);
    cp16(st + ATILE_B + d1, W + g1);
    cp_commit();
}

template <int MODE>
__global__ __launch_bounds__(256, 2)
void gemm_tc(const __half* __restrict__ Ag, const __half* __restrict__ Wg,
             const float* __restrict__ bias, float* __restrict__ C,
             __half* __restrict__ Qp, __half* __restrict__ Kp,
             __half* __restrict__ Vtp)
{
    extern __shared__ char smr[];
    const uint32_t sb = smem_u32(smr);
    const int tid  = threadIdx.x;
    const int wid  = tid >> 5;
    const int lane = tid & 31;
    const int wr = wid >> 2;
    const int wc = wid & 3;
    const int m0 = blockIdx.y * 128;
    const int n0 = blockIdx.x * 128;

    const __half* A = Ag + (size_t)m0 * DIM;
    const __half* W = Wg + (size_t)n0 * DIM;

    float c[4][4][4];
    #pragma unroll
    for (int i = 0; i < 4; i++)
        #pragma unroll
        for (int j = 0; j < 4; j++)
            #pragma unroll
            for (int e = 0; e < 4; e++) c[i][j][e] = 0.f;

    // prologue: 4 chunks in flight
    #pragma unroll
    for (int p = 0; p < 4; p++)
        load_chunk(sb + (uint32_t)p * STAGE_B, A, W, p * 32, tid);

    const uint32_t a_row  = (uint32_t)(lane & 15);
    const uint32_t a_koff = (uint32_t)((lane >> 4) * 8);
    const uint32_t b_row  = (uint32_t)(((lane >> 4) << 3) + (lane & 7));
    const uint32_t b_koff = (uint32_t)(((lane >> 3) & 1) * 8);

    for (int ch = 0; ch < NCHUNK; ch++) {
        cp_wait3();
        __syncthreads();

        const int nc = ch + 4;
        if (nc < NCHUNK)
            load_chunk(sb + (uint32_t)(nc % NSTAGE) * STAGE_B, A, W, nc * 32, tid);
        else
            cp_commit();

        const uint32_t sA = sb + (uint32_t)(ch % NSTAGE) * STAGE_B;
        const uint32_t sW = sA + ATILE_B;

        #pragma unroll
        for (int h = 0; h < 2; h++) {
            const uint32_t acol = (h * 16 + a_koff) * 2;
            const uint32_t bcol = (h * 16 + b_koff) * 2;
            uint32_t a[4][4], b[2][4];
            #pragma unroll
            for (int i = 0; i < 4; i++)
                ldsm4(a[i], sA + (wr * 64 + i * 16 + a_row) * PADB + acol);
            #pragma unroll
            for (int jp = 0; jp < 2; jp++)
                ldsm4(b[jp], sW + (wc * 32 + jp * 16 + b_row) * PADB + bcol);
            #pragma unroll
            for (int i = 0; i < 4; i++) {
                mma16816(c[i][0], a[i], &b[0][0]);
                mma16816(c[i][1], a[i], &b[0][2]);
                mma16816(c[i][2], a[i], &b[1][0]);
                mma16816(c[i][3], a[i], &b[1][2]);
            }
        }
    }
    cp_wait0();

    const int g   = lane >> 2;
    const int tig = lane & 3;

    if (MODE == 0) {
        #pragma unroll
        for (int i = 0; i < 4; i++) {
            const int r0 = m0 + wr * 64 + i * 16 + g;
            #pragma unroll
            for (int j = 0; j < 4; j++) {
                const int cb = n0 + wc * 32 + j * 8 + 2 * tig;
                const float b0 = bias[cb], b1 = bias[cb + 1];
                float2 v0 = make_float2(c[i][j][0] + b0, c[i][j][1] + b1);
                float2 v1 = make_float2(c[i][j][2] + b0, c[i][j][3] + b1);
                *(float2*)(C + (size_t)r0 * DIM + cb)       = v0;
                *(float2*)(C + (size_t)(r0 + 8) * DIM + cb) = v1;
            }
        }
    } else {
        const int sec = n0 >> 10;            // 0=Q, 1=K, 2=V
        const int b   = m0 >> 11;            // batch
        const int sb0 = (m0 & 2047) + wr * 64 + g;
        #pragma unroll
        for (int i = 0; i < 4; i++) {
            const int s = sb0 + i * 16;      // rows s and s+8
            #pragma unroll
            for (int j = 0; j < 4; j++) {
                const int col = n0 + wc * 32 + j * 8 + 2 * tig;
                const int lc  = col & 1023;
                const int h   = lc >> 6;
                const int d   = lc & 63;
                const int bh  = b * NH + h;
                const float b0 = bias[col], b1 = bias[col + 1];
                const float v00 = c[i][j][0] + b0, v01 = c[i][j][1] + b1;
                const float v10 = c[i][j][2] + b0, v11 = c[i][j][3] + b1;
                if (sec < 2) {
                    __half* D = (sec == 0) ? Qp : Kp;
                    const size_t o0 = ((size_t)bh * SEQ + s) * HDIM + d;
                    *(uint32_t*)(D + o0)            = packh2(v00, v01);
                    *(uint32_t*)(D + o0 + 8 * HDIM) = packh2(v10, v11);
                } else {
                    const size_t vb0 = ((size_t)bh * HDIM + d) * SEQ + s;
                    const size_t vb1 = vb0 + SEQ;    // d+1
                    Vtp[vb0]     = __float2half_rn(v00);
                    Vtp[vb1]     = __float2half_rn(v01);
                    Vtp[vb0 + 8] = __float2half_rn(v10);
                    Vtp[vb1 + 8] = __float2half_rn(v11);
                }
            }
        }
    }
}

// ---------------------------------------------------------------------------
// Causal flash attention on fp16 HMMA (single product).
// grid (16, 32): x -> q-tile (reversed, heavy first), y -> (b,h).
// 8 warps x 16 q-rows. 3-stage KV cp.async pipeline, V pre-transposed.
// ---------------------------------------------------------------------------
#define APAD 144
#define ATT_Q_BYTES (128 * APAD)            // 18432
#define ATT_T_BYTES (64 * APAD)             // 9216
#define ATT_STAGE   (2 * ATT_T_BYTES)       // K + V = 18432
#define ATT_NST     3
#define ATT_SMEM    (ATT_Q_BYTES + ATT_NST * ATT_STAGE)   // 73728

__device__ __forceinline__ void load_kv(uint32_t dst,
    const __half* __restrict__ Kp, const __half* __restrict__ Vp,
    int j, int tid)
{
    const int r  = tid >> 2;
    const int c0 = tid & 3;
    const uint32_t ro = (uint32_t)r * APAD;
    const size_t kg = (size_t)(j * 64 + r) * HDIM;
    const size_t vg = (size_t)r * SEQ + j * 64;
    cp16(dst + ro + c0 * 16,                 Kp + kg + c0 * 8);
    cp16(dst + ro + (c0 + 4) * 16,           Kp + kg + (c0 + 4) * 8);
    cp16(dst + ATT_T_BYTES + ro + c0 * 16,       Vp + vg + c0 * 8);
    cp16(dst + ATT_T_BYTES + ro + (c0 + 4) * 16, Vp + vg + (c0 + 4) * 8);
    cp_commit();
}

__global__ __launch_bounds__(256, 2)
void attn_mma(const __half* __restrict__ Q, const __half* __restrict__ K,
              const __half* __restrict__ Vt, __half* __restrict__ O)
{
    extern __shared__ char smr[];
    const uint32_t sbse = smem_u32(smr);
    const uint32_t sQ  = sbse;
    const uint32_t skv = sbse + ATT_Q_BYTES;

    const int tid  = threadIdx.x;
    const int w    = tid >> 5;
    const int lane = tid & 31;
    const int g    = lane >> 2;
    const int t    = lane & 3;
    const int qt   = 15 - blockIdx.x;
    const int bh   = blockIdx.y;
    const int b    = bh >> 4;
    const int h    = bh & 15;

    const __half* Qp = Q + ((size_t)bh * SEQ + qt * 128) * HDIM;
    const __half* Kp = K + (size_t)bh * SEQ * HDIM;
    const __half* Vp = Vt + (size_t)bh * HDIM * SEQ;

    // Q tile (one cp.async group)
    #pragma unroll
    for (int i = 0; i < 4; i++) {
        int idx = tid + i * 256;
        int r = idx >> 3, q = idx & 7;
        cp16(sQ + (uint32_t)r * APAD + q * 16, Qp + (size_t)r * HDIM + q * 8);
    }
    cp_commit();
    load_kv(skv,             Kp, Vp, 0, tid);
    load_kv(skv + ATT_STAGE, Kp, Vp, 1, tid);
    cp_wait2();                              // Q landed
    __syncthreads();

    const uint32_t a_row  = (uint32_t)(lane & 15);
    const uint32_t a_koff = (uint32_t)((lane >> 4) * 8);
    const uint32_t b_row  = (uint32_t)(((lane >> 4) << 3) + (lane & 7));
    const uint32_t b_koff = (uint32_t)(((lane >> 3) & 1) * 8);

    uint32_t qf[4][4];
    #pragma unroll
    for (int h4 = 0; h4 < 4; h4++)
        ldsm4(qf[h4], sQ + (w * 16 + a_row) * APAD + (h4 * 16 + a_koff) * 2);

    float o[8][4];
    #pragma unroll
    for (int nb = 0; nb < 8; nb++)
        #pragma unroll
        for (int e = 0; e < 4; e++) o[nb][e] = 0.f;
    float mi0 = -1e30f, mi1 = -1e30f, li0 = 0.f, li1 = 0.f;

    const int sq0 = qt * 128 + w * 16 + g;
    const int njt = 2 * qt + 2;
    const float CE = 0.125f * 1.4426950408889634f;

    for (int j = 0; j < njt; j++) {
        cp_wait1();
        __syncthreads();

        if (j + 2 < njt)
            load_kv(skv + ((j + 2) % ATT_NST) * ATT_STAGE, Kp, Vp, j + 2, tid);
        else
            cp_commit();

        const uint32_t sK = skv + (j % ATT_NST) * ATT_STAGE;
        const uint32_t sV = sK + ATT_T_BYTES;

        // --- scores ---
        float s[8][4];
        #pragma unroll
        for (int nb = 0; nb < 8; nb++)
            #pragma unroll
            for (int e = 0; e < 4; e++) s[nb][e] = 0.f;

        #pragma unroll
        for (int h4 = 0; h4 < 4; h4++) {
            const uint32_t col = (h4 * 16 + b_koff) * 2;
            #pragma unroll
            for (int jp = 0; jp < 4; jp++) {
                uint32_t kb[4];
                ldsm4(kb, sK + (jp * 16 + b_row) * APAD + col);
                mma16816(s[2 * jp],     qf[h4], kb);
                mma16816(s[2 * jp + 1], qf[h4], kb + 2);
            }
        }

        // --- causal mask ---
        const int kb0 = j * 64 + 2 * t;
        #pragma unroll
        for (int nb = 0; nb < 8; nb++) {
            const int c0 = kb0 + nb * 8;
            if (c0     > sq0)     s[nb][0] = -1e30f;
            if (c0 + 1 > sq0)     s[nb][1] = -1e30f;
            if (c0     > sq0 + 8) s[nb][2] = -1e30f;
            if (c0 + 1 > sq0 + 8) s[nb][3] = -1e30f;
        }

        // --- online softmax ---
        float m0 = -1e30f, m1 = -1e30f;
        #pragma unroll
        for (int nb = 0; nb < 8; nb++) {
            m0 = fmaxf(m0, fmaxf(s[nb][0], s[nb][1]));
            m1 = fmaxf(m1, fmaxf(s[nb][2], s[nb][3]));
        }
        m0 = fmaxf(m0, __shfl_xor_sync(0xFFFFFFFFu, m0, 1));
        m0 = fmaxf(m0, __shfl_xor_sync(0xFFFFFFFFu, m0, 2));
        m1 = fmaxf(m1, __shfl_xor_sync(0xFFFFFFFFu, m1, 1));
        m1 = fmaxf(m1, __shfl_xor_sync(0xFFFFFFFFu, m1, 2));
        const float mn0 = fmaxf(mi0, m0), mn1 = fmaxf(mi1, m1);
        const float corr0 = exp2f((mi0 - mn0) * CE);
        const float corr1 = exp2f((mi1 - mn1) * CE);

        float rs0 = 0.f, rs1 = 0.f;
        #pragma unroll
        for (int nb = 0; nb < 8; nb++) {
            s[nb][0] = exp2f((s[nb][0] - mn0) * CE);
            s[nb][1] = exp2f((s[nb][1] - mn0) * CE);
            s[nb][2] = exp2f((s[nb][2] - mn1) * CE);
            s[nb][3] = exp2f((s[nb][3] - mn1) * CE);
            rs0 += s[nb][0] + s[nb][1];
            rs1 += s[nb][2] + s[nb][3];
        }
        rs0 += __shfl_xor_sync(0xFFFFFFFFu, rs0, 1);
        rs0 += __shfl_xor_sync(0xFFFFFFFFu, rs0, 2);
        rs1 += __shfl_xor_sync(0xFFFFFFFFu, rs1, 1);
        rs1 += __shfl_xor_sync(0xFFFFFFFFu, rs1, 2);
        li0 = li0 * corr0 + rs0;
        li1 = li1 * corr1 + rs1;
        mi0 = mn0; mi1 = mn1;

        #pragma unroll
        for (int nb = 0; nb < 8; nb++) {
            o[nb][0] *= corr0; o[nb][1] *= corr0;
            o[nb][2] *= corr1; o[nb][3] *= corr1;
        }

        // --- P fragments (C-layout -> A-layout, in-register, fp16) ---
        uint32_t pf[4][4];
        #pragma unroll
        for (int h4 = 0; h4 < 4; h4++) {
            pf[h4][0] = packh2(s[2 * h4][0],     s[2 * h4][1]);
            pf[h4][1] = packh2(s[2 * h4][2],     s[2 * h4][3]);
            pf[h4][2] = packh2(s[2 * h4 + 1][0], s[2 * h4 + 1][1]);
            pf[h4][3] = packh2(s[2 * h4 + 1][2], s[2 * h4 + 1][3]);
        }

        // --- P @ V ---
        #pragma unroll
        for (int h4 = 0; h4 < 4; h4++) {
            const uint32_t col = (h4 * 16 + b_koff) * 2;
            #pragma unroll
            for (int jp = 0; jp < 4; jp++) {
                uint32_t vb[4];
                ldsm4(vb, sV + (jp * 16 + b_row) * APAD + col);
                mma16816(o[2 * jp],     pf[h4], vb);
                mma16816(o[2 * jp + 1], pf[h4], vb + 2);
            }
        }
        __syncthreads();
    }

    // epilogue: fp16 output (feeds O-projection)
    const float inv0 = 1.f / li0;
    const float inv1 = 1.f / li1;
    const size_t ob = (size_t)(b * SEQ + sq0) * DIM + h * HDIM;
    #pragma unroll
    for (int nb = 0; nb < 8; nb++) {
        const int d = nb * 8 + 2 * t;
        *(uint32_t*)(O + ob + d)           = packh2(o[nb][0] * inv0, o[nb][1] * inv0);
        *(uint32_t*)(O + ob + 8 * DIM + d) = packh2(o[nb][2] * inv1, o[nb][3] * inv1);
    }
}

// ---------------------------------------------------------------------------
// Launch
// ---------------------------------------------------------------------------
extern "C" void kernel_launch(void* const* d_in, const int* in_sizes, int n_in,
                              void* d_out, int out_size)
{
    const float* X  = (const float*)d_in[0];
    const float* Wq = (const float*)d_in[1];
    const float* bq = (const float*)d_in[2];
    const float* Wk = (const float*)d_in[3];
    const float* bk = (const float*)d_in[4];
    const float* Wv = (const float*)d_in[5];
    const float* bv = (const float*)d_in[6];
    const float* Wo = (const float*)d_in[7];
    const float* bo = (const float*)d_in[8];
    float* out = (float*)d_out;

    float* bias;
    cudaGetSymbolAddress((void**)&bias, g_bias);

    __half *Xh, *Oh, *Wall, *Woh, *Qp, *Kp, *Vtp;
    cudaGetSymbolAddress((void**)&Xh, g_Xh);
    cudaGetSymbolAddress((void**)&Oh, g_Oh);
    cudaGetSymbolAddress((void**)&Wall, g_Wall);
    cudaGetSymbolAddress((void**)&Woh, g_Wo_h);
    cudaGetSymbolAddress((void**)&Qp, g_Q);
    cudaGetSymbolAddress((void**)&Kp, g_K);
    cudaGetSymbolAddress((void**)&Vtp, g_Vt);

    cudaFuncSetAttribute(gemm_tc<0>, cudaFuncAttributeMaxDynamicSharedMemorySize, GEMM_SMEM);
    cudaFuncSetAttribute(gemm_tc<1>, cudaFuncAttributeMaxDynamicSharedMemorySize, GEMM_SMEM);
    cudaFuncSetAttribute(attn_mma, cudaFuncAttributeMaxDynamicSharedMemorySize, ATT_SMEM);

    const int nX4 = MTOT * DIM / 4;      // 1048576
    const int nW4 = DIM * DIM / 4;       // 262144
    const size_t W1 = (size_t)DIM * DIM;

    pack_bias<<<12, 256>>>(bq, bk, bv, bias);
    h_convert<<<nX4 / 256, 256>>>((const float4*)X, (uint32_t*)Xh, nX4);
    h_convert<<<nW4 / 256, 256>>>((const float4*)Wq, (uint32_t*)Wall, nW4);
    h_convert<<<nW4 / 256, 256>>>((const float4*)Wk, (uint32_t*)(Wall + W1), nW4);
    h_convert<<<nW4 / 256, 256>>>((const float4*)Wv, (uint32_t*)(Wall + 2 * W1), nW4);

    // fused QKV projection with per-head scatter epilogue
    gemm_tc<1><<<dim3(3 * DIM / 128, MTOT / 128), 256, GEMM_SMEM>>>(
        Xh, Wall, bias, nullptr, Qp, Kp, Vtp);

    // attention (writes fp16 O)
    attn_mma<<<dim3(SEQ / 128, BATCH * NH), 256, ATT_SMEM>>>(Qp, Kp, Vtp, Oh);

    // Wo convert + output projection (fp32 out)
    h_convert<<<nW4 / 256, 256>>>((const float4*)Wo, (uint32_t*)Woh, nW4);
    gemm_tc<0><<<dim3(DIM / 128, MTOT / 128), 256, GEMM_SMEM>>>(
        Oh, Woh, bo, out, nullptr, nullptr, nullptr);
}

// round 8
// speedup vs baseline: 2.7609x; 1.1457x over previous
#include <cuda_runtime.h>
#include <cuda_fp16.h>
#include <cstdint>

#define BATCH 2
#define SEQ   2048
#define DIM   1024
#define NH    16
#define HDIM  64
#define MTOT  (BATCH * SEQ)   // 4096

// ---------------------------------------------------------------------------
// Scratch (allocation-free __device__ globals), all fp16
// ---------------------------------------------------------------------------
__device__ __align__(16) __half g_Xh[(size_t)MTOT * DIM];
__device__ __align__(16) __half g_Oh[(size_t)MTOT * DIM];          // attn out
__device__ __align__(16) __half g_Wall[(size_t)3 * DIM * DIM];     // Wq|Wk|Wv
__device__ __align__(16) __half g_Wo_h[(size_t)DIM * DIM];
__device__ float g_bias[3 * DIM];

// attention operands, per-head layouts
__device__ __align__(16) __half g_Q[(size_t)BATCH * NH * SEQ * HDIM];
__device__ __align__(16) __half g_K[(size_t)BATCH * NH * SEQ * HDIM];
__device__ __align__(16) __half g_Vt[(size_t)BATCH * NH * HDIM * SEQ];

// ---------------------------------------------------------------------------
// PTX helpers (arch-neutral)
// ---------------------------------------------------------------------------
__device__ __forceinline__ uint32_t smem_u32(const void* p) {
    uint32_t a;
    asm("{ .reg .u64 t; cvta.to.shared.u64 t, %1; cvt.u32.u64 %0, t; }"
        : "=r"(a) : "l"(p));
    return a;
}
__device__ __forceinline__ void cp16(uint32_t dst, const void* src) {
    asm volatile("cp.async.cg.shared.global [%0], [%1], 16;" :: "r"(dst), "l"(src));
}
__device__ __forceinline__ void cp_commit() {
    asm volatile("cp.async.commit_group;" ::: "memory");
}
__device__ __forceinline__ void cp_wait0() {
    asm volatile("cp.async.wait_group 0;" ::: "memory");
}
__device__ __forceinline__ void cp_wait1() {
    asm volatile("cp.async.wait_group 1;" ::: "memory");
}
__device__ __forceinline__ void cp_wait2() {
    asm volatile("cp.async.wait_group 2;" ::: "memory");
}
__device__ __forceinline__ void cp_wait3() {
    asm volatile("cp.async.wait_group 3;" ::: "memory");
}
__device__ __forceinline__ void ldsm4(uint32_t* r, uint32_t addr) {
    asm volatile("ldmatrix.sync.aligned.m8n8.x4.shared.b16 {%0,%1,%2,%3}, [%4];"
        : "=r"(r[0]), "=r"(r[1]), "=r"(r[2]), "=r"(r[3]) : "r"(addr));
}
__device__ __forceinline__ void mma16816(float* d, const uint32_t* a, const uint32_t* b) {
    asm volatile("mma.sync.aligned.m16n8k16.row.col.f32.f16.f16.f32 "
        "{%0,%1,%2,%3}, {%4,%5,%6,%7}, {%8,%9}, {%0,%1,%2,%3};"
        : "+f"(d[0]), "+f"(d[1]), "+f"(d[2]), "+f"(d[3])
        : "r"(a[0]), "r"(a[1]), "r"(a[2]), "r"(a[3]), "r"(b[0]), "r"(b[1]));
}
__device__ __forceinline__ uint32_t packh2(float x, float y) {
    __half2 h = __floats2half2_rn(x, y);
    return *(uint32_t*)&h;
}

// ---------------------------------------------------------------------------
// One merged prep kernel: converts X, Wq, Wk, Wv, Wo to fp16 + packs bias.
// work item = one float4. Layout: [X | Wq | Wk | Wv | Wo].
// ---------------------------------------------------------------------------
#define NX4 (MTOT * DIM / 4)     // 1048576
#define NW4 (DIM * DIM / 4)      // 262144

__global__ __launch_bounds__(256)
void prep_all(const float4* __restrict__ X,
              const float4* __restrict__ Wq, const float4* __restrict__ Wk,
              const float4* __restrict__ Wv, const float4* __restrict__ Wo,
              const float* __restrict__ bq, const float* __restrict__ bk,
              const float* __restrict__ bv,
              uint32_t* __restrict__ Xh, uint32_t* __restrict__ Wall,
              uint32_t* __restrict__ Woh, float* __restrict__ bias)
{
    const int gidx = blockIdx.x * 256 + threadIdx.x;

    if (gidx < 3 * DIM) {
        bias[gidx] = (gidx < DIM) ? bq[gidx]
                   : (gidx < 2 * DIM) ? bk[gidx - DIM] : bv[gidx - 2 * DIM];
    }

    const float4* src;
    uint32_t* dst;
    int li;
    if (gidx < NX4) {
        src = X; dst = Xh; li = gidx;
    } else {
        const int i2 = gidx - NX4;
        const int w  = i2 >> 18;             // NW4 = 2^18
        li = i2 & (NW4 - 1);
        if      (w == 0) { src = Wq; dst = Wall; }
        else if (w == 1) { src = Wk; dst = Wall + (size_t)2 * NW4; }
        else if (w == 2) { src = Wv; dst = Wall + (size_t)4 * NW4; }
        else             { src = Wo; dst = Woh; }
    }
    float4 v = src[li];
    dst[2 * li]     = packh2(v.x, v.y);
    dst[2 * li + 1] = packh2(v.z, v.w);
}

// ---------------------------------------------------------------------------
// fp16 GEMM via mma.sync (validated R7):  C = A @ W^T (+ bias)
// MODE 0: fp32 C[M,DIM] output
// MODE 1: QKV projection; epilogue scatters per-head fp16 Q,K and transposed V
// ---------------------------------------------------------------------------
#define PADB 80
#define ATILE_B (128 * PADB)
#define STAGE_B (2 * ATILE_B)
#define NSTAGE 5
#define GEMM_SMEM (NSTAGE * STAGE_B)         // 102400
#define NCHUNK 32

__device__ __forceinline__ void load_chunk(uint32_t st,
    const __half* __restrict__ A, const __half* __restrict__ W,
    int k0, int tid)
{
    const int r = tid >> 2;
    const int q = tid & 3;
    const uint32_t d0 = (uint32_t)r * PADB + q * 16;
    const uint32_t d1 = (uint32_t)(r + 64) * PADB + q * 16;
    const size_t g0 = (size_t)r * DIM + k0 + q * 8;
    const size_t g1 = (size_t)(r + 64) * DIM + k0 + q * 8;
    cp16(st + d0,           A + g0);
    cp16(st + d1,           A + g1);
    cp16(st + ATILE_B + d0, W + g0);
    cp16(st + ATILE_B + d1, W + g1);
    cp_commit();
}

template <int MODE>
__global__ __launch_bounds__(256, 2)
void gemm_tc(const __half* __restrict__ Ag, const __half* __restrict__ Wg,
             const float* __restrict__ bias, float* __restrict__ C,
             __half* __restrict__ Qp, __half* __restrict__ Kp,
             __half* __restrict__ Vtp)
{
    extern __shared__ char smr[];
    const uint32_t sb = smem_u32(smr);
    const int tid  = threadIdx.x;
    const int wid  = tid >> 5;
    const int lane = tid & 31;
    const int wr = wid >> 2;
    const int wc = wid & 3;
    const int m0 = blockIdx.y * 128;
    const int n0 = blockIdx.x * 128;

    const __half* A = Ag + (size_t)m0 * DIM;
    const __half* W = Wg + (size_t)n0 * DIM;

    float c[4][4][4];
    #pragma unroll
    for (int i = 0; i < 4; i++)
        #pragma unroll
        for (int j = 0; j < 4; j++)
            #pragma unroll
            for (int e = 0; e < 4; e++) c[i][j][e] = 0.f;

    #pragma unroll
    for (int p = 0; p < 4; p++)
        load_chunk(sb + (uint32_t)p * STAGE_B, A, W, p * 32, tid);

    const uint32_t a_row  = (uint32_t)(lane & 15);
    const uint32_t a_koff = (uint32_t)((lane >> 4) * 8);
    const uint32_t b_row  = (uint32_t)(((lane >> 4) << 3) + (lane & 7));
    const uint32_t b_koff = (uint32_t)(((lane >> 3) & 1) * 8);

    for (int ch = 0; ch < NCHUNK; ch++) {
        cp_wait3();
        __syncthreads();

        const int nc = ch + 4;
        if (nc < NCHUNK)
            load_chunk(sb + (uint32_t)(nc % NSTAGE) * STAGE_B, A, W, nc * 32, tid);
        else
            cp_commit();

        const uint32_t sA = sb + (uint32_t)(ch % NSTAGE) * STAGE_B;
        const uint32_t sW = sA + ATILE_B;

        #pragma unroll
        for (int h = 0; h < 2; h++) {
            const uint32_t acol = (h * 16 + a_koff) * 2;
            const uint32_t bcol = (h * 16 + b_koff) * 2;
            uint32_t a[4][4], b[2][4];
            #pragma unroll
            for (int i = 0; i < 4; i++)
                ldsm4(a[i], sA + (wr * 64 + i * 16 + a_row) * PADB + acol);
            #pragma unroll
            for (int jp = 0; jp < 2; jp++)
                ldsm4(b[jp], sW + (wc * 32 + jp * 16 + b_row) * PADB + bcol);
            #pragma unroll
            for (int i = 0; i < 4; i++) {
                mma16816(c[i][0], a[i], &b[0][0]);
                mma16816(c[i][1], a[i], &b[0][2]);
                mma16816(c[i][2], a[i], &b[1][0]);
                mma16816(c[i][3], a[i], &b[1][2]);
            }
        }
    }
    cp_wait0();

    const int g   = lane >> 2;
    const int tig = lane & 3;

    if (MODE == 0) {
        #pragma unroll
        for (int i = 0; i < 4; i++) {
            const int r0 = m0 + wr * 64 + i * 16 + g;
            #pragma unroll
            for (int j = 0; j < 4; j++) {
                const int cb = n0 + wc * 32 + j * 8 + 2 * tig;
                const float b0 = bias[cb], b1 = bias[cb + 1];
                float2 v0 = make_float2(c[i][j][0] + b0, c[i][j][1] + b1);
                float2 v1 = make_float2(c[i][j][2] + b0, c[i][j][3] + b1);
                *(float2*)(C + (size_t)r0 * DIM + cb)       = v0;
                *(float2*)(C + (size_t)(r0 + 8) * DIM + cb) = v1;
            }
        }
    } else {
        const int sec = n0 >> 10;            // 0=Q, 1=K, 2=V
        const int b   = m0 >> 11;            // batch
        const int sb0 = (m0 & 2047) + wr * 64 + g;
        #pragma unroll
        for (int i = 0; i < 4; i++) {
            const int s = sb0 + i * 16;
            #pragma unroll
            for (int j = 0; j < 4; j++) {
                const int col = n0 + wc * 32 + j * 8 + 2 * tig;
                const int lc  = col & 1023;
                const int h   = lc >> 6;
                const int d   = lc & 63;
                const int bh  = b * NH + h;
                const float b0 = bias[col], b1 = bias[col + 1];
                const float v00 = c[i][j][0] + b0, v01 = c[i][j][1] + b1;
                const float v10 = c[i][j][2] + b0, v11 = c[i][j][3] + b1;
                if (sec < 2) {
                    __half* D = (sec == 0) ? Qp : Kp;
                    const size_t o0 = ((size_t)bh * SEQ + s) * HDIM + d;
                    *(uint32_t*)(D + o0)            = packh2(v00, v01);
                    *(uint32_t*)(D + o0 + 8 * HDIM) = packh2(v10, v11);
                } else {
                    const size_t vb0 = ((size_t)bh * HDIM + d) * SEQ + s;
                    const size_t vb1 = vb0 + SEQ;
                    Vtp[vb0]     = __float2half_rn(v00);
                    Vtp[vb1]     = __float2half_rn(v01);
                    Vtp[vb0 + 8] = __float2half_rn(v10);
                    Vtp[vb1 + 8] = __float2half_rn(v11);
                }
            }
        }
    }
}

// ---------------------------------------------------------------------------
// Causal flash attention on fp16 HMMA, BALANCED: each CTA processes q-tiles
// (15 - bx) and (bx) sequentially -> uniform 34 KV-tiles per CTA.
// grid (8, 32) = 256 CTAs = one wave at 2 CTAs/SM.
// ---------------------------------------------------------------------------
#define APAD 144
#define ATT_Q_BYTES (128 * APAD)
#define ATT_T_BYTES (64 * APAD)
#define ATT_STAGE   (2 * ATT_T_BYTES)
#define ATT_NST     3
#define ATT_SMEM    (ATT_Q_BYTES + ATT_NST * ATT_STAGE)   // 73728

__device__ __forceinline__ void load_kv(uint32_t dst,
    const __half* __restrict__ Kp, const __half* __restrict__ Vp,
    int j, int tid)
{
    const int r  = tid >> 2;
    const int c0 = tid & 3;
    const uint32_t ro = (uint32_t)r * APAD;
    const size_t kg = (size_t)(j * 64 + r) * HDIM;
    const size_t vg = (size_t)r * SEQ + j * 64;
    cp16(dst + ro + c0 * 16,                 Kp + kg + c0 * 8);
    cp16(dst + ro + (c0 + 4) * 16,           Kp + kg + (c0 + 4) * 8);
    cp16(dst + ATT_T_BYTES + ro + c0 * 16,       Vp + vg + c0 * 8);
    cp16(dst + ATT_T_BYTES + ro + (c0 + 4) * 16, Vp + vg + (c0 + 4) * 8);
    cp_commit();
}

__device__ __forceinline__ void attn_one_qtile(
    int qt, int b, int h,
    const __half* __restrict__ Q, const __half* __restrict__ Kp,
    const __half* __restrict__ Vp, __half* __restrict__ O,
    uint32_t sQ, uint32_t skv, int tid)
{
    const int w    = tid >> 5;
    const int lane = tid & 31;
    const int g    = lane >> 2;
    const int t    = lane & 3;
    const int bh   = b * NH + h;

    const __half* Qp = Q + ((size_t)bh * SEQ + qt * 128) * HDIM;

    // Q tile (one cp.async group)
    #pragma unroll
    for (int i = 0; i < 4; i++) {
        int idx = tid + i * 256;
        int r = idx >> 3, q = idx & 7;
        cp16(sQ + (uint32_t)r * APAD + q * 16, Qp + (size_t)r * HDIM + q * 8);
    }
    cp_commit();
    load_kv(skv,             Kp, Vp, 0, tid);
    load_kv(skv + ATT_STAGE, Kp, Vp, 1, tid);
    cp_wait2();                              // Q landed
    __syncthreads();

    const uint32_t a_row  = (uint32_t)(lane & 15);
    const uint32_t a_koff = (uint32_t)((lane >> 4) * 8);
    const uint32_t b_row  = (uint32_t)(((lane >> 4) << 3) + (lane & 7));
    const uint32_t b_koff = (uint32_t)(((lane >> 3) & 1) * 8);

    uint32_t qf[4][4];
    #pragma unroll
    for (int h4 = 0; h4 < 4; h4++)
        ldsm4(qf[h4], sQ + (w * 16 + a_row) * APAD + (h4 * 16 + a_koff) * 2);

    float o[8][4];
    #pragma unroll
    for (int nb = 0; nb < 8; nb++)
        #pragma unroll
        for (int e = 0; e < 4; e++) o[nb][e] = 0.f;
    float mi0 = -1e30f, mi1 = -1e30f, li0 = 0.f, li1 = 0.f;

    const int sq0 = qt * 128 + w * 16 + g;
    const int njt = 2 * qt + 2;
    const float CE = 0.125f * 1.4426950408889634f;

    for (int j = 0; j < njt; j++) {
        cp_wait1();
        __syncthreads();

        if (j + 2 < njt)
            load_kv(skv + ((j + 2) % ATT_NST) * ATT_STAGE, Kp, Vp, j + 2, tid);
        else
            cp_commit();

        const uint32_t sK = skv + (j % ATT_NST) * ATT_STAGE;
        const uint32_t sV = sK + ATT_T_BYTES;

        float s[8][4];
        #pragma unroll
        for (int nb = 0; nb < 8; nb++)
            #pragma unroll
            for (int e = 0; e < 4; e++) s[nb][e] = 0.f;

        #pragma unroll
        for (int h4 = 0; h4 < 4; h4++) {
            const uint32_t col = (h4 * 16 + b_koff) * 2;
            #pragma unroll
            for (int jp = 0; jp < 4; jp++) {
                uint32_t kb[4];
                ldsm4(kb, sK + (jp * 16 + b_row) * APAD + col);
                mma16816(s[2 * jp],     qf[h4], kb);
                mma16816(s[2 * jp + 1], qf[h4], kb + 2);
            }
        }

        const int kb0 = j * 64 + 2 * t;
        #pragma unroll
        for (int nb = 0; nb < 8; nb++) {
            const int c0 = kb0 + nb * 8;
            if (c0     > sq0)     s[nb][0] = -1e30f;
            if (c0 + 1 > sq0)     s[nb][1] = -1e30f;
            if (c0     > sq0 + 8) s[nb][2] = -1e30f;
            if (c0 + 1 > sq0 + 8) s[nb][3] = -1e30f;
        }

        float m0 = -1e30f, m1 = -1e30f;
        #pragma unroll
        for (int nb = 0; nb < 8; nb++) {
            m0 = fmaxf(m0, fmaxf(s[nb][0], s[nb][1]));
            m1 = fmaxf(m1, fmaxf(s[nb][2], s[nb][3]));
        }
        m0 = fmaxf(m0, __shfl_xor_sync(0xFFFFFFFFu, m0, 1));
        m0 = fmaxf(m0, __shfl_xor_sync(0xFFFFFFFFu, m0, 2));
        m1 = fmaxf(m1, __shfl_xor_sync(0xFFFFFFFFu, m1, 1));
        m1 = fmaxf(m1, __shfl_xor_sync(0xFFFFFFFFu, m1, 2));
        const float mn0 = fmaxf(mi0, m0), mn1 = fmaxf(mi1, m1);
        const float corr0 = exp2f((mi0 - mn0) * CE);
        const float corr1 = exp2f((mi1 - mn1) * CE);

        float rs0 = 0.f, rs1 = 0.f;
        #pragma unroll
        for (int nb = 0; nb < 8; nb++) {
            s[nb][0] = exp2f((s[nb][0] - mn0) * CE);
            s[nb][1] = exp2f((s[nb][1] - mn0) * CE);
            s[nb][2] = exp2f((s[nb][2] - mn1) * CE);
            s[nb][3] = exp2f((s[nb][3] - mn1) * CE);
            rs0 += s[nb][0] + s[nb][1];
            rs1 += s[nb][2] + s[nb][3];
        }
        rs0 += __shfl_xor_sync(0xFFFFFFFFu, rs0, 1);
        rs0 += __shfl_xor_sync(0xFFFFFFFFu, rs0, 2);
        rs1 += __shfl_xor_sync(0xFFFFFFFFu, rs1, 1);
        rs1 += __shfl_xor_sync(0xFFFFFFFFu, rs1, 2);
        li0 = li0 * corr0 + rs0;
        li1 = li1 * corr1 + rs1;
        mi0 = mn0; mi1 = mn1;

        #pragma unroll
        for (int nb = 0; nb < 8; nb++) {
            o[nb][0] *= corr0; o[nb][1] *= corr0;
            o[nb][2] *= corr1; o[nb][3] *= corr1;
        }

        uint32_t pf[4][4];
        #pragma unroll
        for (int h4 = 0; h4 < 4; h4++) {
            pf[h4][0] = packh2(s[2 * h4][0],     s[2 * h4][1]);
            pf[h4][1] = packh2(s[2 * h4][2],     s[2 * h4][3]);
            pf[h4][2] = packh2(s[2 * h4 + 1][0], s[2 * h4 + 1][1]);
            pf[h4][3] = packh2(s[2 * h4 + 1][2], s[2 * h4 + 1][3]);
        }

        #pragma unroll
        for (int h4 = 0; h4 < 4; h4++) {
            const uint32_t col = (h4 * 16 + b_koff) * 2;
            #pragma unroll
            for (int jp = 0; jp < 4; jp++) {
                uint32_t vb[4];
                ldsm4(vb, sV + (jp * 16 + b_row) * APAD + col);
                mma16816(o[2 * jp],     pf[h4], vb);
                mma16816(o[2 * jp + 1], pf[h4], vb + 2);
            }
        }
        __syncthreads();
    }

    // drain pipeline so the next q-tile starts with clean group bookkeeping
    cp_wait0();
    __syncthreads();

    const float inv0 = 1.f / li0;
    const float inv1 = 1.f / li1;
    const size_t ob = (size_t)(b * SEQ + sq0) * DIM + h * HDIM;
    #pragma unroll
    for (int nb = 0; nb < 8; nb++) {
        const int d = nb * 8 + 2 * t;
        *(uint32_t*)(O + ob + d)           = packh2(o[nb][0] * inv0, o[nb][1] * inv0);
        *(uint32_t*)(O + ob + 8 * DIM + d) = packh2(o[nb][2] * inv1, o[nb][3] * inv1);
    }
}

__global__ __launch_bounds__(256, 2)
void attn_mma(const __half* __restrict__ Q, const __half* __restrict__ K,
              const __half* __restrict__ Vt, __half* __restrict__ O)
{
    extern __shared__ char smr[];
    const uint32_t sbse = smem_u32(smr);
    const uint32_t sQ  = sbse;
    const uint32_t skv = sbse + ATT_Q_BYTES;

    const int tid = threadIdx.x;
    const int bx  = blockIdx.x;          // 0..7
    const int bh  = blockIdx.y;
    const int b   = bh >> 4;
    const int h   = bh & 15;

    const __half* Kp = K + (size_t)bh * SEQ * HDIM;
    const __half* Vp = Vt + (size_t)bh * HDIM * SEQ;

    // heavy tile first, then its light partner: uniform 34 KV-tiles per CTA
    attn_one_qtile(15 - bx, b, h, Q, Kp, Vp, O, sQ, skv, tid);
    attn_one_qtile(bx,      b, h, Q, Kp, Vp, O, sQ, skv, tid);
}

// ---------------------------------------------------------------------------
// Launch
// ---------------------------------------------------------------------------
extern "C" void kernel_launch(void* const* d_in, const int* in_sizes, int n_in,
                              void* d_out, int out_size)
{
    const float* X  = (const float*)d_in[0];
    const float* Wq = (const float*)d_in[1];
    const float* bq = (const float*)d_in[2];
    const float* Wk = (const float*)d_in[3];
    const float* bk = (const float*)d_in[4];
    const float* Wv = (const float*)d_in[5];
    const float* bv = (const float*)d_in[6];
    const float* Wo = (const float*)d_in[7];
    const float* bo = (const float*)d_in[8];
    float* out = (float*)d_out;

    float* bias;
    cudaGetSymbolAddress((void**)&bias, g_bias);

    __half *Xh, *Oh, *Wall, *Woh, *Qp, *Kp, *Vtp;
    cudaGetSymbolAddress((void**)&Xh, g_Xh);
    cudaGetSymbolAddress((void**)&Oh, g_Oh);
    cudaGetSymbolAddress((void**)&Wall, g_Wall);
    cudaGetSymbolAddress((void**)&Woh, g_Wo_h);
    cudaGetSymbolAddress((void**)&Qp, g_Q);
    cudaGetSymbolAddress((void**)&Kp, g_K);
    cudaGetSymbolAddress((void**)&Vtp, g_Vt);

    cudaFuncSetAttribute(gemm_tc<0>, cudaFuncAttributeMaxDynamicSharedMemorySize, GEMM_SMEM);
    cudaFuncSetAttribute(gemm_tc<1>, cudaFuncAttributeMaxDynamicSharedMemorySize, GEMM_SMEM);
    cudaFuncSetAttribute(attn_mma, cudaFuncAttributeMaxDynamicSharedMemorySize, ATT_SMEM);

    // one merged prep launch (X + 4 W converts + bias pack)
    prep_all<<<(NX4 + 4 * NW4) / 256, 256>>>(
        (const float4*)X, (const float4*)Wq, (const float4*)Wk,
        (const float4*)Wv, (const float4*)Wo, bq, bk, bv,
        (uint32_t*)Xh, (uint32_t*)Wall, (uint32_t*)Woh, bias);

    // fused QKV projection with per-head scatter epilogue
    gemm_tc<1><<<dim3(3 * DIM / 128, MTOT / 128), 256, GEMM_SMEM>>>(
        Xh, Wall, bias, nullptr, Qp, Kp, Vtp);

    // balanced attention (writes fp16 O)
    attn_mma<<<dim3(8, BATCH * NH), 256, ATT_SMEM>>>(Qp, Kp, Vtp, Oh);

    // output projection (fp32 out)
    gemm_tc<0><<<dim3(DIM / 128, MTOT / 128), 256, GEMM_SMEM>>>(
        Oh, Woh, bo, out, nullptr, nullptr, nullptr);
}

// round 9
// speedup vs baseline: 2.9910x; 1.0833x over previous
#include <cuda_runtime.h>
#include <cuda_fp16.h>
#include <cstdint>

#define BATCH 2
#define SEQ   2048
#define DIM   1024
#define NH    16
#define HDIM  64
#define MTOT  (BATCH * SEQ)   // 4096

// ---------------------------------------------------------------------------
// Scratch (allocation-free __device__ globals), all fp16
// ---------------------------------------------------------------------------
__device__ __align__(16) __half g_Xh[(size_t)MTOT * DIM];
__device__ __align__(16) __half g_Oh[(size_t)MTOT * DIM];          // attn out
__device__ __align__(16) __half g_Wall[(size_t)3 * DIM * DIM];     // Wq|Wk|Wv
__device__ __align__(16) __half g_Wo_h[(size_t)DIM * DIM];
__device__ float g_bias[3 * DIM];

// attention operands, per-head layouts
__device__ __align__(16) __half g_Q[(size_t)BATCH * NH * SEQ * HDIM];
__device__ __align__(16) __half g_K[(size_t)BATCH * NH * SEQ * HDIM];
__device__ __align__(16) __half g_Vt[(size_t)BATCH * NH * HDIM * SEQ];

// ---------------------------------------------------------------------------
// PTX helpers (arch-neutral)
// ---------------------------------------------------------------------------
__device__ __forceinline__ uint32_t smem_u32(const void* p) {
    uint32_t a;
    asm("{ .reg .u64 t; cvta.to.shared.u64 t, %1; cvt.u32.u64 %0, t; }"
        : "=r"(a) : "l"(p));
    return a;
}
__device__ __forceinline__ void cp16(uint32_t dst, const void* src) {
    asm volatile("cp.async.cg.shared.global [%0], [%1], 16;" :: "r"(dst), "l"(src));
}
__device__ __forceinline__ void cp_commit() {
    asm volatile("cp.async.commit_group;" ::: "memory");
}
__device__ __forceinline__ void cp_wait0() {
    asm volatile("cp.async.wait_group 0;" ::: "memory");
}
__device__ __forceinline__ void cp_wait1() {
    asm volatile("cp.async.wait_group 1;" ::: "memory");
}
__device__ __forceinline__ void cp_wait2() {
    asm volatile("cp.async.wait_group 2;" ::: "memory");
}
__device__ __forceinline__ void ldsm4(uint32_t* r, uint32_t addr) {
    asm volatile("ldmatrix.sync.aligned.m8n8.x4.shared.b16 {%0,%1,%2,%3}, [%4];"
        : "=r"(r[0]), "=r"(r[1]), "=r"(r[2]), "=r"(r[3]) : "r"(addr));
}
__device__ __forceinline__ void mma16816(float* d, const uint32_t* a, const uint32_t* b) {
    asm volatile("mma.sync.aligned.m16n8k16.row.col.f32.f16.f16.f32 "
        "{%0,%1,%2,%3}, {%4,%5,%6,%7}, {%8,%9}, {%0,%1,%2,%3};"
        : "+f"(d[0]), "+f"(d[1]), "+f"(d[2]), "+f"(d[3])
        : "r"(a[0]), "r"(a[1]), "r"(a[2]), "r"(a[3]), "r"(b[0]), "r"(b[1]));
}
__device__ __forceinline__ uint32_t packh2(float x, float y) {
    __half2 h = __floats2half2_rn(x, y);
    return *(uint32_t*)&h;
}
__device__ __forceinline__ void ex2h2(uint32_t& v) {
    asm("ex2.approx.f16x2 %0, %0;" : "+r"(v));
}

// ---------------------------------------------------------------------------
// One merged prep kernel: converts X, Wq, Wk, Wv, Wo to fp16 + packs bias.
// ---------------------------------------------------------------------------
#define NX4 (MTOT * DIM / 4)     // 1048576
#define NW4 (DIM * DIM / 4)      // 262144

__global__ __launch_bounds__(256)
void prep_all(const float4* __restrict__ X,
              const float4* __restrict__ Wq, const float4* __restrict__ Wk,
              const float4* __restrict__ Wv, const float4* __restrict__ Wo,
              const float* __restrict__ bq, const float* __restrict__ bk,
              const float* __restrict__ bv,
              uint32_t* __restrict__ Xh, uint32_t* __restrict__ Wall,
              uint32_t* __restrict__ Woh, float* __restrict__ bias)
{
    const int gidx = blockIdx.x * 256 + threadIdx.x;

    if (gidx < 3 * DIM) {
        bias[gidx] = (gidx < DIM) ? bq[gidx]
                   : (gidx < 2 * DIM) ? bk[gidx - DIM] : bv[gidx - 2 * DIM];
    }

    const float4* src;
    uint32_t* dst;
    int li;
    if (gidx < NX4) {
        src = X; dst = Xh; li = gidx;
    } else {
        const int i2 = gidx - NX4;
        const int w  = i2 >> 18;             // NW4 = 2^18
        li = i2 & (NW4 - 1);
        if      (w == 0) { src = Wq; dst = Wall; }
        else if (w == 1) { src = Wk; dst = Wall + (size_t)2 * NW4; }
        else if (w == 2) { src = Wv; dst = Wall + (size_t)4 * NW4; }
        else             { src = Wo; dst = Woh; }
    }
    float4 v = src[li];
    dst[2 * li]     = packh2(v.x, v.y);
    dst[2 * li + 1] = packh2(v.z, v.w);
}

// ---------------------------------------------------------------------------
// fp16 GEMM via mma.sync:  C = A @ W^T (+ bias)
// BK=64 chunks (half the syncs of BK=32), 3-stage cp.async, 2 CTAs/SM.
// MODE 0: fp32 C[M,DIM] output
// MODE 1: QKV projection; epilogue scatters per-head fp16 Q,K and transposed V
// ---------------------------------------------------------------------------
#define PADB 144
#define ATILE_B (128 * PADB)                 // 18432
#define STAGE_B (2 * ATILE_B)                // 36864
#define NSTAGE 3
#define GEMM_SMEM (NSTAGE * STAGE_B)         // 110592
#define NCHUNK 16                            // K=1024 / 64

__device__ __forceinline__ void load_chunk(uint32_t st,
    const __half* __restrict__ A, const __half* __restrict__ W,
    int k0, int tid)
{
    #pragma unroll
    for (int t = 0; t < 4; t++) {
        const int idx = tid + t * 256;
        const int r = idx >> 3;              // 0..127
        const int q = idx & 7;               // 16B eighth of 128B row
        const uint32_t d = (uint32_t)r * PADB + q * 16;
        const size_t  g = (size_t)r * DIM + k0 + q * 8;
        cp16(st + d,           A + g);
        cp16(st + ATILE_B + d, W + g);
    }
    cp_commit();
}

template <int MODE>
__global__ __launch_bounds__(256, 2)
void gemm_tc(const __half* __restrict__ Ag, const __half* __restrict__ Wg,
             const float* __restrict__ bias, float* __restrict__ C,
             __half* __restrict__ Qp, __half* __restrict__ Kp,
             __half* __restrict__ Vtp)
{
    extern __shared__ char smr[];
    const uint32_t sb = smem_u32(smr);
    const int tid  = threadIdx.x;
    const int wid  = tid >> 5;
    const int lane = tid & 31;
    const int wr = wid >> 2;
    const int wc = wid & 3;
    const int m0 = blockIdx.y * 128;
    const int n0 = blockIdx.x * 128;

    const __half* A = Ag + (size_t)m0 * DIM;
    const __half* W = Wg + (size_t)n0 * DIM;

    float c[4][4][4];
    #pragma unroll
    for (int i = 0; i < 4; i++)
        #pragma unroll
        for (int j = 0; j < 4; j++)
            #pragma unroll
            for (int e = 0; e < 4; e++) c[i][j][e] = 0.f;

    load_chunk(sb,           A, W, 0,  tid);
    load_chunk(sb + STAGE_B, A, W, 64, tid);

    const uint32_t a_row  = (uint32_t)(lane & 15);
    const uint32_t a_koff = (uint32_t)((lane >> 4) * 8);
    const uint32_t b_row  = (uint32_t)(((lane >> 4) << 3) + (lane & 7));
    const uint32_t b_koff = (uint32_t)(((lane >> 3) & 1) * 8);

    for (int ch = 0; ch < NCHUNK; ch++) {
        cp_wait1();
        __syncthreads();

        const int nc = ch + 2;
        if (nc < NCHUNK)
            load_chunk(sb + (uint32_t)(nc % NSTAGE) * STAGE_B, A, W, nc * 64, tid);
        else
            cp_commit();

        const uint32_t sA = sb + (uint32_t)(ch % NSTAGE) * STAGE_B;
        const uint32_t sW = sA + ATILE_B;

        #pragma unroll
        for (int h = 0; h < 4; h++) {
            const uint32_t acol = (h * 16 + a_koff) * 2;
            const uint32_t bcol = (h * 16 + b_koff) * 2;
            uint32_t a[4][4], b[2][4];
            #pragma unroll
            for (int i = 0; i < 4; i++)
                ldsm4(a[i], sA + (wr * 64 + i * 16 + a_row) * PADB + acol);
            #pragma unroll
            for (int jp = 0; jp < 2; jp++)
                ldsm4(b[jp], sW + (wc * 32 + jp * 16 + b_row) * PADB + bcol);
            #pragma unroll
            for (int i = 0; i < 4; i++) {
                mma16816(c[i][0], a[i], &b[0][0]);
                mma16816(c[i][1], a[i], &b[0][2]);
                mma16816(c[i][2], a[i], &b[1][0]);
                mma16816(c[i][3], a[i], &b[1][2]);
            }
        }
    }
    cp_wait0();

    const int g   = lane >> 2;
    const int tig = lane & 3;

    if (MODE == 0) {
        #pragma unroll
        for (int i = 0; i < 4; i++) {
            const int r0 = m0 + wr * 64 + i * 16 + g;
            #pragma unroll
            for (int j = 0; j < 4; j++) {
                const int cb = n0 + wc * 32 + j * 8 + 2 * tig;
                const float b0 = bias[cb], b1 = bias[cb + 1];
                float2 v0 = make_float2(c[i][j][0] + b0, c[i][j][1] + b1);
                float2 v1 = make_float2(c[i][j][2] + b0, c[i][j][3] + b1);
                *(float2*)(C + (size_t)r0 * DIM + cb)       = v0;
                *(float2*)(C + (size_t)(r0 + 8) * DIM + cb) = v1;
            }
        }
    } else {
        const int sec = n0 >> 10;            // 0=Q, 1=K, 2=V
        const int b   = m0 >> 11;            // batch
        const int sb0 = (m0 & 2047) + wr * 64 + g;
        #pragma unroll
        for (int i = 0; i < 4; i++) {
            const int s = sb0 + i * 16;
            #pragma unroll
            for (int j = 0; j < 4; j++) {
                const int col = n0 + wc * 32 + j * 8 + 2 * tig;
                const int lc  = col & 1023;
                const int h   = lc >> 6;
                const int d   = lc & 63;
                const int bh  = b * NH + h;
                const float b0 = bias[col], b1 = bias[col + 1];
                const float v00 = c[i][j][0] + b0, v01 = c[i][j][1] + b1;
                const float v10 = c[i][j][2] + b0, v11 = c[i][j][3] + b1;
                if (sec < 2) {
                    __half* D = (sec == 0) ? Qp : Kp;
                    const size_t o0 = ((size_t)bh * SEQ + s) * HDIM + d;
                    *(uint32_t*)(D + o0)            = packh2(v00, v01);
                    *(uint32_t*)(D + o0 + 8 * HDIM) = packh2(v10, v11);
                } else {
                    const size_t vb0 = ((size_t)bh * HDIM + d) * SEQ + s;
                    const size_t vb1 = vb0 + SEQ;
                    Vtp[vb0]     = __float2half_rn(v00);
                    Vtp[vb1]     = __float2half_rn(v01);
                    Vtp[vb0 + 8] = __float2half_rn(v10);
                    Vtp[vb1 + 8] = __float2half_rn(v11);
                }
            }
        }
    }
}

// ---------------------------------------------------------------------------
// Causal flash attention on fp16 HMMA.
// - fused-sum column: constant ones B-fragment; accumulator column 0 carries
//   the softmax denominator through the o = o*corr + P@V recurrence.
// - P via ex2.approx.f16x2 (half the MUFU work, no pack converts).
// Balanced: CTA handles q-tiles (15-bx) then (bx); grid (8,32) = one wave.
// ---------------------------------------------------------------------------
#define APAD 144
#define ATT_Q_BYTES (128 * APAD)
#define ATT_T_BYTES (64 * APAD)
#define ATT_STAGE   (2 * ATT_T_BYTES)
#define ATT_NST     3
#define ATT_SMEM    (ATT_Q_BYTES + ATT_NST * ATT_STAGE)   // 73728

__device__ __forceinline__ void load_kv(uint32_t dst,
    const __half* __restrict__ Kp, const __half* __restrict__ Vp,
    int j, int tid)
{
    const int r  = tid >> 2;
    const int c0 = tid & 3;
    const uint32_t ro = (uint32_t)r * APAD;
    const size_t kg = (size_t)(j * 64 + r) * HDIM;
    const size_t vg = (size_t)r * SEQ + j * 64;
    cp16(dst + ro + c0 * 16,                 Kp + kg + c0 * 8);
    cp16(dst + ro + (c0 + 4) * 16,           Kp + kg + (c0 + 4) * 8);
    cp16(dst + ATT_T_BYTES + ro + c0 * 16,       Vp + vg + c0 * 8);
    cp16(dst + ATT_T_BYTES + ro + (c0 + 4) * 16, Vp + vg + (c0 + 4) * 8);
    cp_commit();
}

__device__ __forceinline__ void attn_one_qtile(
    int qt, int b, int h,
    const __half* __restrict__ Q, const __half* __restrict__ Kp,
    const __half* __restrict__ Vp, __half* __restrict__ O,
    uint32_t sQ, uint32_t skv, int tid)
{
    const int w    = tid >> 5;
    const int lane = tid & 31;
    const int g    = lane >> 2;
    const int t    = lane & 3;
    const int bh   = b * NH + h;

    const __half* Qp = Q + ((size_t)bh * SEQ + qt * 128) * HDIM;

    #pragma unroll
    for (int i = 0; i < 4; i++) {
        int idx = tid + i * 256;
        int r = idx >> 3, q = idx & 7;
        cp16(sQ + (uint32_t)r * APAD + q * 16, Qp + (size_t)r * HDIM + q * 8);
    }
    cp_commit();
    load_kv(skv,             Kp, Vp, 0, tid);
    load_kv(skv + ATT_STAGE, Kp, Vp, 1, tid);
    cp_wait2();                              // Q landed
    __syncthreads();

    const uint32_t a_row  = (uint32_t)(lane & 15);
    const uint32_t a_koff = (uint32_t)((lane >> 4) * 8);
    const uint32_t b_row  = (uint32_t)(((lane >> 4) << 3) + (lane & 7));
    const uint32_t b_koff = (uint32_t)(((lane >> 3) & 1) * 8);

    // constant "ones row at n=0" B-fragment (row.col: n = lane>>2)
    const uint32_t bones[2] = { (lane < 4) ? 0x3C003C00u : 0u,
                                (lane < 4) ? 0x3C003C00u : 0u };

    uint32_t qf[4][4];
    #pragma unroll
    for (int h4 = 0; h4 < 4; h4++)
        ldsm4(qf[h4], sQ + (w * 16 + a_row) * APAD + (h4 * 16 + a_koff) * 2);

    float o[8][4];
    #pragma unroll
    for (int nb = 0; nb < 8; nb++)
        #pragma unroll
        for (int e = 0; e < 4; e++) o[nb][e] = 0.f;
    float lac[4] = {0.f, 0.f, 0.f, 0.f};     // fused-sum column accumulator
    float mi0 = -1e30f, mi1 = -1e30f;

    const int sq0 = qt * 128 + w * 16 + g;
    const int njt = 2 * qt + 2;
    const float CE = 0.125f * 1.4426950408889634f;

    for (int j = 0; j < njt; j++) {
        cp_wait1();
        __syncthreads();

        if (j + 2 < njt)
            load_kv(skv + ((j + 2) % ATT_NST) * ATT_STAGE, Kp, Vp, j + 2, tid);
        else
            cp_commit();

        const uint32_t sK = skv + (j % ATT_NST) * ATT_STAGE;
        const uint32_t sV = sK + ATT_T_BYTES;

        // --- scores ---
        float s[8][4];
        #pragma unroll
        for (int nb = 0; nb < 8; nb++)
            #pragma unroll
            for (int e = 0; e < 4; e++) s[nb][e] = 0.f;

        #pragma unroll
        for (int h4 = 0; h4 < 4; h4++) {
            const uint32_t col = (h4 * 16 + b_koff) * 2;
            #pragma unroll
            for (int jp = 0; jp < 4; jp++) {
                uint32_t kb[4];
                ldsm4(kb, sK + (jp * 16 + b_row) * APAD + col);
                mma16816(s[2 * jp],     qf[h4], kb);
                mma16816(s[2 * jp + 1], qf[h4], kb + 2);
            }
        }

        // --- causal mask ---
        const int kb0 = j * 64 + 2 * t;
        #pragma unroll
        for (int nb = 0; nb < 8; nb++) {
            const int c0 = kb0 + nb * 8;
            if (c0     > sq0)     s[nb][0] = -1e30f;
            if (c0 + 1 > sq0)     s[nb][1] = -1e30f;
            if (c0     > sq0 + 8) s[nb][2] = -1e30f;
            if (c0 + 1 > sq0 + 8) s[nb][3] = -1e30f;
        }

        // --- running max + rescale ---
        float m0 = -1e30f, m1 = -1e30f;
        #pragma unroll
        for (int nb = 0; nb < 8; nb++) {
            m0 = fmaxf(m0, fmaxf(s[nb][0], s[nb][1]));
            m1 = fmaxf(m1, fmaxf(s[nb][2], s[nb][3]));
        }
        m0 = fmaxf(m0, __shfl_xor_sync(0xFFFFFFFFu, m0, 1));
        m0 = fmaxf(m0, __shfl_xor_sync(0xFFFFFFFFu, m0, 2));
        m1 = fmaxf(m1, __shfl_xor_sync(0xFFFFFFFFu, m1, 1));
        m1 = fmaxf(m1, __shfl_xor_sync(0xFFFFFFFFu, m1, 2));
        const float mn0 = fmaxf(mi0, m0), mn1 = fmaxf(mi1, m1);
        const float corr0 = exp2f((mi0 - mn0) * CE);
        const float corr1 = exp2f((mi1 - mn1) * CE);
        mi0 = mn0; mi1 = mn1;

        #pragma unroll
        for (int nb = 0; nb < 8; nb++) {
            o[nb][0] *= corr0; o[nb][1] *= corr0;
            o[nb][2] *= corr1; o[nb][3] *= corr1;
        }
        lac[0] *= corr0; lac[1] *= corr0;
        lac[2] *= corr1; lac[3] *= corr1;

        // --- P fragments: pack args, one ex2.approx.f16x2 per pair ---
        uint32_t pf[4][4];
        #pragma unroll
        for (int h4 = 0; h4 < 4; h4++) {
            pf[h4][0] = packh2((s[2 * h4][0]     - mn0) * CE, (s[2 * h4][1]     - mn0) * CE);
            pf[h4][1] = packh2((s[2 * h4][2]     - mn1) * CE, (s[2 * h4][3]     - mn1) * CE);
            pf[h4][2] = packh2((s[2 * h4 + 1][0] - mn0) * CE, (s[2 * h4 + 1][1] - mn0) * CE);
            pf[h4][3] = packh2((s[2 * h4 + 1][2] - mn1) * CE, (s[2 * h4 + 1][3] - mn1) * CE);
            ex2h2(pf[h4][0]); ex2h2(pf[h4][1]);
            ex2h2(pf[h4][2]); ex2h2(pf[h4][3]);
        }

        // --- P @ [V | 1] ---
        #pragma unroll
        for (int h4 = 0; h4 < 4; h4++) {
            const uint32_t col = (h4 * 16 + b_koff) * 2;
            #pragma unroll
            for (int jp = 0; jp < 4; jp++) {
                uint32_t vb[4];
                ldsm4(vb, sV + (jp * 16 + b_row) * APAD + col);
                mma16816(o[2 * jp],     pf[h4], vb);
                mma16816(o[2 * jp + 1], pf[h4], vb + 2);
            }
            mma16816(lac, pf[h4], bones);    // fused denominator column
        }
        __syncthreads();
    }

    cp_wait0();
    __syncthreads();

    // broadcast denominator (column 0 lives in quad lane t=0)
    const int ql = lane & ~3;
    const float li0 = __shfl_sync(0xFFFFFFFFu, lac[0], ql);
    const float li1 = __shfl_sync(0xFFFFFFFFu, lac[2], ql);
    const float inv0 = 1.f / li0;
    const float inv1 = 1.f / li1;
    const size_t ob = (size_t)(b * SEQ + sq0) * DIM + h * HDIM;
    #pragma unroll
    for (int nb = 0; nb < 8; nb++) {
        const int d = nb * 8 + 2 * t;
        *(uint32_t*)(O + ob + d)           = packh2(o[nb][0] * inv0, o[nb][1] * inv0);
        *(uint32_t*)(O + ob + 8 * DIM + d) = packh2(o[nb][2] * inv1, o[nb][3] * inv1);
    }
}

__global__ __launch_bounds__(256, 2)
void attn_mma(const __half* __restrict__ Q, const __half* __restrict__ K,
              const __half* __restrict__ Vt, __half* __restrict__ O)
{
    extern __shared__ char smr[];
    const uint32_t sbse = smem_u32(smr);
    const uint32_t sQ  = sbse;
    const uint32_t skv = sbse + ATT_Q_BYTES;

    const int tid = threadIdx.x;
    const int bx  = blockIdx.x;          // 0..7
    const int bh  = blockIdx.y;
    const int b   = bh >> 4;
    const int h   = bh & 15;

    const __half* Kp = K + (size_t)bh * SEQ * HDIM;
    const __half* Vp = Vt + (size_t)bh * HDIM * SEQ;

    attn_one_qtile(15 - bx, b, h, Q, Kp, Vp, O, sQ, skv, tid);
    attn_one_qtile(bx,      b, h, Q, Kp, Vp, O, sQ, skv, tid);
}

// ---------------------------------------------------------------------------
// Launch
// ---------------------------------------------------------------------------
extern "C" void kernel_launch(void* const* d_in, const int* in_sizes, int n_in,
                              void* d_out, int out_size)
{
    const float* X  = (const float*)d_in[0];
    const float* Wq = (const float*)d_in[1];
    const float* bq = (const float*)d_in[2];
    const float* Wk = (const float*)d_in[3];
    const float* bk = (const float*)d_in[4];
    const float* Wv = (const float*)d_in[5];
    const float* bv = (const float*)d_in[6];
    const float* Wo = (const float*)d_in[7];
    const float* bo = (const float*)d_in[8];
    float* out = (float*)d_out;

    float* bias;
    cudaGetSymbolAddress((void**)&bias, g_bias);

    __half *Xh, *Oh, *Wall, *Woh, *Qp, *Kp, *Vtp;
    cudaGetSymbolAddress((void**)&Xh, g_Xh);
    cudaGetSymbolAddress((void**)&Oh, g_Oh);
    cudaGetSymbolAddress((void**)&Wall, g_Wall);
    cudaGetSymbolAddress((void**)&Woh, g_Wo_h);
    cudaGetSymbolAddress((void**)&Qp, g_Q);
    cudaGetSymbolAddress((void**)&Kp, g_K);
    cudaGetSymbolAddress((void**)&Vtp, g_Vt);

    cudaFuncSetAttribute(gemm_tc<0>, cudaFuncAttributeMaxDynamicSharedMemorySize, GEMM_SMEM);
    cudaFuncSetAttribute(gemm_tc<1>, cudaFuncAttributeMaxDynamicSharedMemorySize, GEMM_SMEM);
    cudaFuncSetAttribute(attn_mma, cudaFuncAttributeMaxDynamicSharedMemorySize, ATT_SMEM);

    prep_all<<<(NX4 + 4 * NW4) / 256, 256>>>(
        (const float4*)X, (const float4*)Wq, (const float4*)Wk,
        (const float4*)Wv, (const float4*)Wo, bq, bk, bv,
        (uint32_t*)Xh, (uint32_t*)Wall, (uint32_t*)Woh, bias);

    gemm_tc<1><<<dim3(3 * DIM / 128, MTOT / 128), 256, GEMM_SMEM>>>(
        Xh, Wall, bias, nullptr, Qp, Kp, Vtp);

    attn_mma<<<dim3(8, BATCH * NH), 256, ATT_SMEM>>>(Qp, Kp, Vtp, Oh);

    gemm_tc<0><<<dim3(DIM / 128, MTOT / 128), 256, GEMM_SMEM>>>(
        Oh, Woh, bo, out, nullptr, nullptr, nullptr);
}